// round 1
// baseline (speedup 1.0000x reference)
#include <cuda_runtime.h>
#include <cuda_bf16.h>
#include <math.h>

// Problem constants
#define BB 4
#define SS 2048
#define DD 1024
#define HH 16
#define DK 64
#define MM (BB * SS)          // 8192 rows
#define NEG_BIG (-1.0e30f)

// ---------------- scratch (alloc-free: __device__ globals) ----------------
__device__ float g_q[BB * HH * SS * DK];     // [b,h,s,dk]
__device__ float g_k[BB * HH * SS * DK];
__device__ float g_v[BB * HH * SS * DK];
__device__ float g_attn[MM * DD];            // [b*s, h*dk] row-major

// ---------------- GEMM: C[M,N] = A[M,K] * W[N,K]^T ----------------
// M=8192, N=1024, K=1024. BM=BN=128, BK=16, 256 threads, 8x8 per thread.
// SCATTER=1: write into [b,h,s,dk] layout. SCATTER=0: plain row-major [M,N].
template <int SCATTER>
__global__ __launch_bounds__(256) void gemm_nt(const float* __restrict__ A,
                                               const float* __restrict__ W,
                                               float* __restrict__ C) {
    __shared__ float As[16][128];
    __shared__ float Bs[16][128];

    const int tid = threadIdx.x;
    const int tx = tid & 15;        // 0..15 (col groups)
    const int ty = tid >> 4;        // 0..15 (row groups)
    const int row0 = blockIdx.y * 128;
    const int col0 = blockIdx.x * 128;

    float acc[8][8];
#pragma unroll
    for (int i = 0; i < 8; i++)
#pragma unroll
        for (int j = 0; j < 8; j++) acc[i][j] = 0.0f;

    for (int kt = 0; kt < DD; kt += 16) {
        __syncthreads();
#pragma unroll
        for (int t = 0; t < 2; t++) {
            int idx = tid + t * 256;       // 0..511
            int r = idx >> 2;              // 0..127
            int c4 = idx & 3;              // 0..3
            float4 va = *(const float4*)(A + (size_t)(row0 + r) * DD + kt + c4 * 4);
            As[c4 * 4 + 0][r] = va.x;
            As[c4 * 4 + 1][r] = va.y;
            As[c4 * 4 + 2][r] = va.z;
            As[c4 * 4 + 3][r] = va.w;
            float4 vb = *(const float4*)(W + (size_t)(col0 + r) * DD + kt + c4 * 4);
            Bs[c4 * 4 + 0][r] = vb.x;
            Bs[c4 * 4 + 1][r] = vb.y;
            Bs[c4 * 4 + 2][r] = vb.z;
            Bs[c4 * 4 + 3][r] = vb.w;
        }
        __syncthreads();
#pragma unroll
        for (int k = 0; k < 16; k++) {
            float a[8], b[8];
            *(float4*)&a[0] = *(const float4*)&As[k][ty * 8];
            *(float4*)&a[4] = *(const float4*)&As[k][ty * 8 + 4];
            *(float4*)&b[0] = *(const float4*)&Bs[k][tx * 8];
            *(float4*)&b[4] = *(const float4*)&Bs[k][tx * 8 + 4];
#pragma unroll
            for (int i = 0; i < 8; i++)
#pragma unroll
                for (int j = 0; j < 8; j++) acc[i][j] += a[i] * b[j];
        }
    }

    // epilogue
#pragma unroll
    for (int i = 0; i < 8; i++) {
        int r = row0 + ty * 8 + i;
#pragma unroll
        for (int j4 = 0; j4 < 2; j4++) {
            int c = col0 + tx * 8 + j4 * 4;
            float4 v = make_float4(acc[i][j4 * 4 + 0], acc[i][j4 * 4 + 1],
                                   acc[i][j4 * 4 + 2], acc[i][j4 * 4 + 3]);
            if (SCATTER) {
                // r -> (b, s); c -> (h, d). dst [b,h,s,dk]
                int b = r >> 11;           // /2048
                int s = r & 2047;
                int h = c >> 6;            // /64
                int d = c & 63;
                size_t off = (((size_t)(b * HH + h) * SS + s) * DK + d);
                *(float4*)(C + off) = v;
            } else {
                *(float4*)(C + (size_t)r * DD + c) = v;
            }
        }
    }
}

// ---------------- Flash attention (causal), fp32 ----------------
// grid: (S/64, B*H), 256 threads. BM=BN=64, dk=64, 4x4 per thread.
// smem (dynamic): Qt[64][65] (k-major), Kt[64][65] (k-major; reused as P),
//                 Vs[64][65] (row-major). 49920 bytes.
#define LD5 65

__global__ __launch_bounds__(256) void attn_kernel(const float* __restrict__ Q,
                                                   const float* __restrict__ K,
                                                   const float* __restrict__ V,
                                                   float* __restrict__ O) {
    extern __shared__ float sm[];
    float* Qt = sm;                 // [k][r]
    float* Kt = sm + 64 * LD5;      // [k][c]; later P as [c][r]
    float* Vs = sm + 2 * 64 * LD5;  // [j][d]

    const int tid = threadIdx.x;
    const int tx = tid & 15;
    const int ty = tid >> 4;
    const int qt = 31 - blockIdx.x;      // longest blocks first
    const int bh = blockIdx.y;
    const int q0 = qt * 64;

    const float* Qb = Q + (size_t)bh * SS * DK;
    const float* Kb = K + (size_t)bh * SS * DK;
    const float* Vb = V + (size_t)bh * SS * DK;

    // load Q tile (scaled by 1/sqrt(dk)=0.125), transposed
    for (int idx = tid; idx < 64 * 64; idx += 256) {
        int r = idx >> 6, c = idx & 63;
        Qt[c * LD5 + r] = Qb[(size_t)(q0 + r) * DK + c] * 0.125f;
    }

    float m[4], l[4], o[4][4];
#pragma unroll
    for (int i = 0; i < 4; i++) {
        m[i] = NEG_BIG;
        l[i] = 0.0f;
#pragma unroll
        for (int j = 0; j < 4; j++) o[i][j] = 0.0f;
    }

    for (int t = 0; t <= qt; t++) {
        const int kv0 = t * 64;
        __syncthreads();   // prev PV done (and Q load visible on t=0 after next sync)
        for (int idx = tid; idx < 64 * 64; idx += 256) {
            int r = idx >> 6, c = idx & 63;
            float kvval = Kb[(size_t)(kv0 + r) * DK + c];
            Kt[c * LD5 + r] = kvval;
            Vs[r * LD5 + c] = Vb[(size_t)(kv0 + r) * DK + c];
        }
        __syncthreads();

        // S = Q K^T  (pre-scaled)
        float acc[4][4];
#pragma unroll
        for (int i = 0; i < 4; i++)
#pragma unroll
            for (int j = 0; j < 4; j++) acc[i][j] = 0.0f;

#pragma unroll 8
        for (int k = 0; k < 64; k++) {
            float qv[4], kv[4];
#pragma unroll
            for (int i = 0; i < 4; i++) qv[i] = Qt[k * LD5 + ty * 4 + i];
#pragma unroll
            for (int j = 0; j < 4; j++) kv[j] = Kt[k * LD5 + tx * 4 + j];
#pragma unroll
            for (int i = 0; i < 4; i++)
#pragma unroll
                for (int j = 0; j < 4; j++) acc[i][j] += qv[i] * kv[j];
        }

        if (t == qt) {  // diagonal tile: mask col > row
#pragma unroll
            for (int i = 0; i < 4; i++)
#pragma unroll
                for (int j = 0; j < 4; j++)
                    if (tx * 4 + j > ty * 4 + i) acc[i][j] = NEG_BIG;
        }

        // online softmax update (reduce over 16-lane tx groups)
#pragma unroll
        for (int i = 0; i < 4; i++) {
            float mx = fmaxf(fmaxf(acc[i][0], acc[i][1]), fmaxf(acc[i][2], acc[i][3]));
#pragma unroll
            for (int off = 8; off > 0; off >>= 1)
                mx = fmaxf(mx, __shfl_xor_sync(0xffffffffu, mx, off));
            float mn = fmaxf(m[i], mx);
            float corr = __expf(m[i] - mn);
            m[i] = mn;
            float rs = 0.0f;
#pragma unroll
            for (int j = 0; j < 4; j++) {
                float e = __expf(acc[i][j] - mn);
                acc[i][j] = e;
                rs += e;
            }
#pragma unroll
            for (int off = 8; off > 0; off >>= 1)
                rs += __shfl_xor_sync(0xffffffffu, rs, off);
            l[i] = l[i] * corr + rs;
#pragma unroll
            for (int j = 0; j < 4; j++) o[i][j] *= corr;
        }

        __syncthreads();   // everyone done reading Kt
        // store P transposed into Kt buffer: P[c][r]
#pragma unroll
        for (int i = 0; i < 4; i++)
#pragma unroll
            for (int j = 0; j < 4; j++)
                Kt[(tx * 4 + j) * LD5 + ty * 4 + i] = acc[i][j];
        __syncthreads();

        // O += P V
#pragma unroll 8
        for (int jj = 0; jj < 64; jj++) {
            float pv[4], vv[4];
#pragma unroll
            for (int i = 0; i < 4; i++) pv[i] = Kt[jj * LD5 + ty * 4 + i];
#pragma unroll
            for (int j = 0; j < 4; j++) vv[j] = Vs[jj * LD5 + tx * 4 + j];
#pragma unroll
            for (int i = 0; i < 4; i++)
#pragma unroll
                for (int j = 0; j < 4; j++) o[i][j] += pv[i] * vv[j];
        }
    }

    // write to g_attn [b*s, h*64+d]
    const int b = bh >> 4, h = bh & 15;
#pragma unroll
    for (int i = 0; i < 4; i++) {
        float inv = 1.0f / l[i];
        int s = q0 + ty * 4 + i;
        size_t base = ((size_t)(b * SS + s)) * DD + h * DK;
#pragma unroll
        for (int j = 0; j < 4; j++) O[base + tx * 4 + j] = o[i][j] * inv;
    }
}

// ---------------- launch ----------------
extern "C" void kernel_launch(void* const* d_in, const int* in_sizes, int n_in,
                              void* d_out, int out_size) {
    const float* x  = (const float*)d_in[0];
    const float* wq = (const float*)d_in[1];
    const float* wk = (const float*)d_in[2];
    const float* wv = (const float*)d_in[3];
    const float* wo = (const float*)d_in[4];
    float* out = (float*)d_out;

    float *pq, *pk, *pv, *pa;
    cudaGetSymbolAddress((void**)&pq, g_q);
    cudaGetSymbolAddress((void**)&pk, g_k);
    cudaGetSymbolAddress((void**)&pv, g_v);
    cudaGetSymbolAddress((void**)&pa, g_attn);

    static const int attn_smem = 3 * 64 * LD5 * sizeof(float);  // 49920
    cudaFuncSetAttribute(attn_kernel, cudaFuncAttributeMaxDynamicSharedMemorySize,
                         attn_smem);

    dim3 gGemm(DD / 128, MM / 128);   // (8, 64)

    gemm_nt<1><<<gGemm, 256>>>(x, wq, pq);
    gemm_nt<1><<<gGemm, 256>>>(x, wk, pk);
    gemm_nt<1><<<gGemm, 256>>>(x, wv, pv);

    dim3 gAttn(SS / 64, BB * HH);     // (32, 64)
    attn_kernel<<<gAttn, 256, attn_smem>>>(pq, pk, pv, pa);

    gemm_nt<0><<<gGemm, 256>>>(pa, wo, out);
}

// round 2
// speedup vs baseline: 1.5460x; 1.5460x over previous
#include <cuda_runtime.h>
#include <cuda_bf16.h>
#include <math.h>

// Problem constants
#define BB 4
#define SS 2048
#define DD 1024
#define HH 16
#define DK 64
#define MM (BB * SS)          // 8192 rows
#define NEG_BIG (-1.0e30f)

// ---------------- scratch (alloc-free: __device__ globals) ----------------
__device__ float g_q[BB * HH * SS * DK];     // [b,h,s,dk]
__device__ float g_k[BB * HH * SS * DK];
__device__ float g_v[BB * HH * SS * DK];
__device__ float g_attn[MM * DD];            // [b*s, h*dk] row-major

// ---------------- tf32 helpers ----------------
__device__ __forceinline__ unsigned f2tf32(float f) {
    unsigned r;
    asm("cvt.rna.tf32.f32 %0, %1;" : "=r"(r) : "f"(f));
    return r;
}

__device__ __forceinline__ void mma_m16n8k8(float* d, const unsigned* a,
                                            const unsigned* b) {
    asm volatile(
        "mma.sync.aligned.m16n8k8.row.col.f32.tf32.tf32.f32 "
        "{%0,%1,%2,%3},{%4,%5,%6,%7},{%8,%9},{%0,%1,%2,%3};\n"
        : "+f"(d[0]), "+f"(d[1]), "+f"(d[2]), "+f"(d[3])
        : "r"(a[0]), "r"(a[1]), "r"(a[2]), "r"(a[3]), "r"(b[0]), "r"(b[1]));
}

// ---------------- GEMM: C[M,N] = A[M,K] * W[N,K]^T via tf32 tensor cores ----
// M=8192, N=1024, K=1024. BM=BN=128, BK=16, 256 threads (8 warps).
// Warp layout 2(m)x4(n): warp tile 64x32 = 4x4 tiles of m16n8k8.
// smem stride 20 floats -> fragment loads are bank-conflict-free.
// SCATTER=1: write into [b,h,s,dk] layout. SCATTER=0: row-major [M,N].
#define GLD 20

template <int SCATTER>
__global__ __launch_bounds__(256, 2) void gemm_tf32(const float* __restrict__ A,
                                                    const float* __restrict__ W,
                                                    float* __restrict__ C) {
    __shared__ float As[128][GLD];
    __shared__ float Ws[128][GLD];

    const int tid = threadIdx.x;
    const int lane = tid & 31;
    const int wid = tid >> 5;
    const int g = lane >> 2;       // 0..7
    const int tig = lane & 3;      // 0..3
    const int wm0 = (wid >> 2) * 64;   // 0 or 64
    const int wn0 = (wid & 3) * 32;    // 0,32,64,96
    const int row0 = blockIdx.y * 128;
    const int col0 = blockIdx.x * 128;

    float acc[4][4][4];
#pragma unroll
    for (int im = 0; im < 4; im++)
#pragma unroll
        for (int jn = 0; jn < 4; jn++)
#pragma unroll
            for (int q = 0; q < 4; q++) acc[im][jn][q] = 0.0f;

    // load-slot geometry: idx = tid + i*256; r = idx>>2 (0..127); c4 = idx&3
    float4 pa[2], pw[2];
#pragma unroll
    for (int i = 0; i < 2; i++) {
        int idx = tid + i * 256;
        int r = idx >> 2, c4 = idx & 3;
        pa[i] = *(const float4*)(A + (size_t)(row0 + r) * DD + c4 * 4);
        pw[i] = *(const float4*)(W + (size_t)(col0 + r) * DD + c4 * 4);
    }

    for (int kt = 0; kt < DD; kt += 16) {
        // store prefetched tile to smem with tf32 rounding
#pragma unroll
        for (int i = 0; i < 2; i++) {
            int idx = tid + i * 256;
            int r = idx >> 2, c4 = idx & 3;
            As[r][c4 * 4 + 0] = __uint_as_float(f2tf32(pa[i].x));
            As[r][c4 * 4 + 1] = __uint_as_float(f2tf32(pa[i].y));
            As[r][c4 * 4 + 2] = __uint_as_float(f2tf32(pa[i].z));
            As[r][c4 * 4 + 3] = __uint_as_float(f2tf32(pa[i].w));
            Ws[r][c4 * 4 + 0] = __uint_as_float(f2tf32(pw[i].x));
            Ws[r][c4 * 4 + 1] = __uint_as_float(f2tf32(pw[i].y));
            Ws[r][c4 * 4 + 2] = __uint_as_float(f2tf32(pw[i].z));
            Ws[r][c4 * 4 + 3] = __uint_as_float(f2tf32(pw[i].w));
        }
        __syncthreads();

        // prefetch next k-tile from gmem (overlaps with MMA below)
        if (kt + 16 < DD) {
#pragma unroll
            for (int i = 0; i < 2; i++) {
                int idx = tid + i * 256;
                int r = idx >> 2, c4 = idx & 3;
                pa[i] = *(const float4*)(A + (size_t)(row0 + r) * DD + kt + 16 + c4 * 4);
                pw[i] = *(const float4*)(W + (size_t)(col0 + r) * DD + kt + 16 + c4 * 4);
            }
        }

        // compute: 2 k8-steps of 16 MMAs
#pragma unroll
        for (int k8 = 0; k8 < 16; k8 += 8) {
            unsigned af[4][4], bf[4][2];
#pragma unroll
            for (int im = 0; im < 4; im++) {
                int rb = wm0 + im * 16;
                af[im][0] = __float_as_uint(As[rb + g][k8 + tig]);
                af[im][1] = __float_as_uint(As[rb + g + 8][k8 + tig]);
                af[im][2] = __float_as_uint(As[rb + g][k8 + tig + 4]);
                af[im][3] = __float_as_uint(As[rb + g + 8][k8 + tig + 4]);
            }
#pragma unroll
            for (int jn = 0; jn < 4; jn++) {
                int cb = wn0 + jn * 8;
                bf[jn][0] = __float_as_uint(Ws[cb + g][k8 + tig]);
                bf[jn][1] = __float_as_uint(Ws[cb + g][k8 + tig + 4]);
            }
#pragma unroll
            for (int im = 0; im < 4; im++)
#pragma unroll
                for (int jn = 0; jn < 4; jn++)
                    mma_m16n8k8(acc[im][jn], af[im], bf[jn]);
        }
        __syncthreads();
    }

    // epilogue: each lane owns rows (g, g+8) of each m16 tile, cols 2*tig..2*tig+1
#pragma unroll
    for (int im = 0; im < 4; im++) {
#pragma unroll
        for (int jn = 0; jn < 4; jn++) {
            int r = row0 + wm0 + im * 16 + g;
            int c = col0 + wn0 + jn * 8 + 2 * tig;
#pragma unroll
            for (int half = 0; half < 2; half++) {
                int rr = r + half * 8;
                float2 v = make_float2(acc[im][jn][half * 2 + 0],
                                       acc[im][jn][half * 2 + 1]);
                if (SCATTER) {
                    int b = rr >> 11;          // /2048
                    int s = rr & 2047;
                    int h = c >> 6;            // /64
                    int d = c & 63;
                    size_t off = (((size_t)(b * HH + h) * SS + s) * DK + d);
                    *(float2*)(C + off) = v;
                } else {
                    *(float2*)(C + (size_t)rr * DD + c) = v;
                }
            }
        }
    }
}

// ---------------- Flash attention (causal), fp32 ----------------
// grid: (S/64, B*H), 256 threads. BM=BN=64, dk=64, 4x4 per thread.
#define LD5 65

__global__ __launch_bounds__(256) void attn_kernel(const float* __restrict__ Q,
                                                   const float* __restrict__ K,
                                                   const float* __restrict__ V,
                                                   float* __restrict__ O) {
    extern __shared__ float sm[];
    float* Qt = sm;                 // [k][r]
    float* Kt = sm + 64 * LD5;      // [k][c]; later P as [c][r]
    float* Vs = sm + 2 * 64 * LD5;  // [j][d]

    const int tid = threadIdx.x;
    const int tx = tid & 15;
    const int ty = tid >> 4;
    const int qt = 31 - blockIdx.x;      // longest blocks first
    const int bh = blockIdx.y;
    const int q0 = qt * 64;

    const float* Qb = Q + (size_t)bh * SS * DK;
    const float* Kb = K + (size_t)bh * SS * DK;
    const float* Vb = V + (size_t)bh * SS * DK;

    for (int idx = tid; idx < 64 * 64; idx += 256) {
        int r = idx >> 6, c = idx & 63;
        Qt[c * LD5 + r] = Qb[(size_t)(q0 + r) * DK + c] * 0.125f;
    }

    float m[4], l[4], o[4][4];
#pragma unroll
    for (int i = 0; i < 4; i++) {
        m[i] = NEG_BIG;
        l[i] = 0.0f;
#pragma unroll
        for (int j = 0; j < 4; j++) o[i][j] = 0.0f;
    }

    for (int t = 0; t <= qt; t++) {
        const int kv0 = t * 64;
        __syncthreads();
        for (int idx = tid; idx < 64 * 64; idx += 256) {
            int r = idx >> 6, c = idx & 63;
            Kt[c * LD5 + r] = Kb[(size_t)(kv0 + r) * DK + c];
            Vs[r * LD5 + c] = Vb[(size_t)(kv0 + r) * DK + c];
        }
        __syncthreads();

        float acc[4][4];
#pragma unroll
        for (int i = 0; i < 4; i++)
#pragma unroll
            for (int j = 0; j < 4; j++) acc[i][j] = 0.0f;

#pragma unroll 8
        for (int k = 0; k < 64; k++) {
            float qv[4], kv[4];
#pragma unroll
            for (int i = 0; i < 4; i++) qv[i] = Qt[k * LD5 + ty * 4 + i];
#pragma unroll
            for (int j = 0; j < 4; j++) kv[j] = Kt[k * LD5 + tx * 4 + j];
#pragma unroll
            for (int i = 0; i < 4; i++)
#pragma unroll
                for (int j = 0; j < 4; j++) acc[i][j] += qv[i] * kv[j];
        }

        if (t == qt) {
#pragma unroll
            for (int i = 0; i < 4; i++)
#pragma unroll
                for (int j = 0; j < 4; j++)
                    if (tx * 4 + j > ty * 4 + i) acc[i][j] = NEG_BIG;
        }

#pragma unroll
        for (int i = 0; i < 4; i++) {
            float mx = fmaxf(fmaxf(acc[i][0], acc[i][1]), fmaxf(acc[i][2], acc[i][3]));
#pragma unroll
            for (int off = 8; off > 0; off >>= 1)
                mx = fmaxf(mx, __shfl_xor_sync(0xffffffffu, mx, off));
            float mn = fmaxf(m[i], mx);
            float corr = __expf(m[i] - mn);
            m[i] = mn;
            float rs = 0.0f;
#pragma unroll
            for (int j = 0; j < 4; j++) {
                float e = __expf(acc[i][j] - mn);
                acc[i][j] = e;
                rs += e;
            }
#pragma unroll
            for (int off = 8; off > 0; off >>= 1)
                rs += __shfl_xor_sync(0xffffffffu, rs, off);
            l[i] = l[i] * corr + rs;
#pragma unroll
            for (int j = 0; j < 4; j++) o[i][j] *= corr;
        }

        __syncthreads();
#pragma unroll
        for (int i = 0; i < 4; i++)
#pragma unroll
            for (int j = 0; j < 4; j++)
                Kt[(tx * 4 + j) * LD5 + ty * 4 + i] = acc[i][j];
        __syncthreads();

#pragma unroll 8
        for (int jj = 0; jj < 64; jj++) {
            float pv[4], vv[4];
#pragma unroll
            for (int i = 0; i < 4; i++) pv[i] = Kt[jj * LD5 + ty * 4 + i];
#pragma unroll
            for (int j = 0; j < 4; j++) vv[j] = Vs[jj * LD5 + tx * 4 + j];
#pragma unroll
            for (int i = 0; i < 4; i++)
#pragma unroll
                for (int j = 0; j < 4; j++) o[i][j] += pv[i] * vv[j];
        }
    }

    const int b = bh >> 4, h = bh & 15;
#pragma unroll
    for (int i = 0; i < 4; i++) {
        float inv = 1.0f / l[i];
        int s = q0 + ty * 4 + i;
        size_t base = ((size_t)(b * SS + s)) * DD + h * DK;
#pragma unroll
        for (int j = 0; j < 4; j++) O[base + tx * 4 + j] = o[i][j] * inv;
    }
}

// ---------------- launch ----------------
extern "C" void kernel_launch(void* const* d_in, const int* in_sizes, int n_in,
                              void* d_out, int out_size) {
    const float* x  = (const float*)d_in[0];
    const float* wq = (const float*)d_in[1];
    const float* wk = (const float*)d_in[2];
    const float* wv = (const float*)d_in[3];
    const float* wo = (const float*)d_in[4];
    float* out = (float*)d_out;

    float *pq, *pk, *pv, *pa;
    cudaGetSymbolAddress((void**)&pq, g_q);
    cudaGetSymbolAddress((void**)&pk, g_k);
    cudaGetSymbolAddress((void**)&pv, g_v);
    cudaGetSymbolAddress((void**)&pa, g_attn);

    static const int attn_smem = 3 * 64 * LD5 * sizeof(float);  // 49920
    cudaFuncSetAttribute(attn_kernel, cudaFuncAttributeMaxDynamicSharedMemorySize,
                         attn_smem);

    dim3 gGemm(DD / 128, MM / 128);   // (8, 64)

    gemm_tf32<1><<<gGemm, 256>>>(x, wq, pq);
    gemm_tf32<1><<<gGemm, 256>>>(x, wk, pk);
    gemm_tf32<1><<<gGemm, 256>>>(x, wv, pv);

    dim3 gAttn(SS / 64, BB * HH);     // (32, 64)
    attn_kernel<<<gAttn, 256, attn_smem>>>(pq, pk, pv, pa);

    gemm_tf32<0><<<gGemm, 256>>>(pa, wo, out);
}

// round 6
// speedup vs baseline: 2.6894x; 1.7396x over previous
#include <cuda_runtime.h>
#include <cuda_bf16.h>
#include <math.h>

// Problem constants
#define BB 4
#define SS 2048
#define DD 1024
#define HH 16
#define DK 64
#define MM (BB * SS)          // 8192 rows
#define NEG_BIG (-1.0e30f)

// ---------------- scratch (alloc-free: __device__ globals) ----------------
__device__ float g_q[BB * HH * SS * DK];     // [b,h,s,dk]
__device__ float g_k[BB * HH * SS * DK];
__device__ float g_v[BB * HH * SS * DK];
__device__ float g_attn[MM * DD];            // [b*s, h*dk] row-major

// ---------------- tf32 helpers ----------------
__device__ __forceinline__ unsigned f2tf32(float f) {
    unsigned r;
    asm("cvt.rna.tf32.f32 %0, %1;" : "=r"(r) : "f"(f));
    return r;
}

__device__ __forceinline__ void mma_m16n8k8(float* d, const unsigned* a,
                                            const unsigned* b) {
    asm volatile(
        "mma.sync.aligned.m16n8k8.row.col.f32.tf32.tf32.f32 "
        "{%0,%1,%2,%3},{%4,%5,%6,%7},{%8,%9},{%0,%1,%2,%3};\n"
        : "+f"(d[0]), "+f"(d[1]), "+f"(d[2]), "+f"(d[3])
        : "r"(a[0]), "r"(a[1]), "r"(a[2]), "r"(a[3]), "r"(b[0]), "r"(b[1]));
}

// ---------------- GEMM: C[M,N] = A[M,K] * W[N,K]^T via tf32 tensor cores ----
#define GLD 20

template <int SCATTER>
__global__ __launch_bounds__(256, 2) void gemm_tf32(const float* __restrict__ A,
                                                    const float* __restrict__ W,
                                                    float* __restrict__ C) {
    __shared__ float As[128][GLD];
    __shared__ float Ws[128][GLD];

    const int tid = threadIdx.x;
    const int lane = tid & 31;
    const int wid = tid >> 5;
    const int g = lane >> 2;
    const int tig = lane & 3;
    const int wm0 = (wid >> 2) * 64;
    const int wn0 = (wid & 3) * 32;
    const int row0 = blockIdx.y * 128;
    const int col0 = blockIdx.x * 128;

    float acc[4][4][4];
#pragma unroll
    for (int im = 0; im < 4; im++)
#pragma unroll
        for (int jn = 0; jn < 4; jn++)
#pragma unroll
            for (int q = 0; q < 4; q++) acc[im][jn][q] = 0.0f;

    float4 pa[2], pw[2];
#pragma unroll
    for (int i = 0; i < 2; i++) {
        int idx = tid + i * 256;
        int r = idx >> 2, c4 = idx & 3;
        pa[i] = *(const float4*)(A + (size_t)(row0 + r) * DD + c4 * 4);
        pw[i] = *(const float4*)(W + (size_t)(col0 + r) * DD + c4 * 4);
    }

    for (int kt = 0; kt < DD; kt += 16) {
#pragma unroll
        for (int i = 0; i < 2; i++) {
            int idx = tid + i * 256;
            int r = idx >> 2, c4 = idx & 3;
            As[r][c4 * 4 + 0] = __uint_as_float(f2tf32(pa[i].x));
            As[r][c4 * 4 + 1] = __uint_as_float(f2tf32(pa[i].y));
            As[r][c4 * 4 + 2] = __uint_as_float(f2tf32(pa[i].z));
            As[r][c4 * 4 + 3] = __uint_as_float(f2tf32(pa[i].w));
            Ws[r][c4 * 4 + 0] = __uint_as_float(f2tf32(pw[i].x));
            Ws[r][c4 * 4 + 1] = __uint_as_float(f2tf32(pw[i].y));
            Ws[r][c4 * 4 + 2] = __uint_as_float(f2tf32(pw[i].z));
            Ws[r][c4 * 4 + 3] = __uint_as_float(f2tf32(pw[i].w));
        }
        __syncthreads();

        if (kt + 16 < DD) {
#pragma unroll
            for (int i = 0; i < 2; i++) {
                int idx = tid + i * 256;
                int r = idx >> 2, c4 = idx & 3;
                pa[i] = *(const float4*)(A + (size_t)(row0 + r) * DD + kt + 16 + c4 * 4);
                pw[i] = *(const float4*)(W + (size_t)(col0 + r) * DD + kt + 16 + c4 * 4);
            }
        }

#pragma unroll
        for (int k8 = 0; k8 < 16; k8 += 8) {
            unsigned af[4][4], bf[4][2];
#pragma unroll
            for (int im = 0; im < 4; im++) {
                int rb = wm0 + im * 16;
                af[im][0] = __float_as_uint(As[rb + g][k8 + tig]);
                af[im][1] = __float_as_uint(As[rb + g + 8][k8 + tig]);
                af[im][2] = __float_as_uint(As[rb + g][k8 + tig + 4]);
                af[im][3] = __float_as_uint(As[rb + g + 8][k8 + tig + 4]);
            }
#pragma unroll
            for (int jn = 0; jn < 4; jn++) {
                int cb = wn0 + jn * 8;
                bf[jn][0] = __float_as_uint(Ws[cb + g][k8 + tig]);
                bf[jn][1] = __float_as_uint(Ws[cb + g][k8 + tig + 4]);
            }
#pragma unroll
            for (int im = 0; im < 4; im++)
#pragma unroll
                for (int jn = 0; jn < 4; jn++)
                    mma_m16n8k8(acc[im][jn], af[im], bf[jn]);
        }
        __syncthreads();
    }

#pragma unroll
    for (int im = 0; im < 4; im++) {
#pragma unroll
        for (int jn = 0; jn < 4; jn++) {
            int r = row0 + wm0 + im * 16 + g;
            int c = col0 + wn0 + jn * 8 + 2 * tig;
#pragma unroll
            for (int half = 0; half < 2; half++) {
                int rr = r + half * 8;
                float2 v = make_float2(acc[im][jn][half * 2 + 0],
                                       acc[im][jn][half * 2 + 1]);
                if (SCATTER) {
                    int b = rr >> 11;
                    int s = rr & 2047;
                    int h = c >> 6;
                    int d = c & 63;
                    size_t off = (((size_t)(b * HH + h) * SS + s) * DK + d);
                    *(float2*)(C + off) = v;
                } else {
                    *(float2*)(C + (size_t)rr * DD + c) = v;
                }
            }
        }
    }
}

// ---------------- Flash attention (causal) via tf32 mma ----------------
// BM=128, BN=64, dk=64. 256 threads = 8 warps; warp w owns rows [16w,16w+16).
// smem stride 68: frag-load bank = 4*g + tig (bijective over warp) -> conflict-free.
#define ALD 68

__global__ __launch_bounds__(256) void attn_mma(const float* __restrict__ Q,
                                                const float* __restrict__ K,
                                                const float* __restrict__ V,
                                                float* __restrict__ O) {
    extern __shared__ float sm[];
    float* Qs = sm;                    // [128][ALD]  (tf32, pre-scaled)
    float* Ks = Qs + 128 * ALD;        // [64][ALD]   (tf32)
    float* Vs = Ks + 64 * ALD;         // [64][ALD]   (tf32, row-major [j][d])
    float* Ps = Vs + 64 * ALD;         // [128][ALD]  (tf32 probabilities)

    const int tid = threadIdx.x;
    const int lane = tid & 31;
    const int wid = tid >> 5;
    const int g = lane >> 2;        // 0..7
    const int tig = lane & 3;       // 0..3
    const int qb = (gridDim.x - 1) - blockIdx.x;   // longest blocks first
    const int bh = blockIdx.y;
    const int q0 = qb * 128;
    const int row_base = wid * 16;

    const float* Qb = Q + (size_t)bh * SS * DK;
    const float* Kb = K + (size_t)bh * SS * DK;
    const float* Vb = V + (size_t)bh * SS * DK;

    // load Q tile, scale by 1/8, tf32-round
    for (int idx = tid; idx < 128 * 16; idx += 256) {
        int r = idx >> 4, c4 = (idx & 15) * 4;
        float4 v = *(const float4*)(Qb + (size_t)(q0 + r) * DK + c4);
        Qs[r * ALD + c4 + 0] = __uint_as_float(f2tf32(v.x * 0.125f));
        Qs[r * ALD + c4 + 1] = __uint_as_float(f2tf32(v.y * 0.125f));
        Qs[r * ALD + c4 + 2] = __uint_as_float(f2tf32(v.z * 0.125f));
        Qs[r * ALD + c4 + 3] = __uint_as_float(f2tf32(v.w * 0.125f));
    }

    float m_i[2] = {NEG_BIG, NEG_BIG};
    float l_i[2] = {0.0f, 0.0f};
    float oacc[8][4];
#pragma unroll
    for (int jn = 0; jn < 8; jn++)
#pragma unroll
        for (int q = 0; q < 4; q++) oacc[jn][q] = 0.0f;

    const int nt = 2 * qb + 2;
    for (int t = 0; t < nt; t++) {
        const int kv0 = t * 64;
        __syncthreads();
        for (int idx = tid; idx < 64 * 16; idx += 256) {
            int r = idx >> 4, c4 = (idx & 15) * 4;
            float4 kv = *(const float4*)(Kb + (size_t)(kv0 + r) * DK + c4);
            float4 vv = *(const float4*)(Vb + (size_t)(kv0 + r) * DK + c4);
            Ks[r * ALD + c4 + 0] = __uint_as_float(f2tf32(kv.x));
            Ks[r * ALD + c4 + 1] = __uint_as_float(f2tf32(kv.y));
            Ks[r * ALD + c4 + 2] = __uint_as_float(f2tf32(kv.z));
            Ks[r * ALD + c4 + 3] = __uint_as_float(f2tf32(kv.w));
            Vs[r * ALD + c4 + 0] = __uint_as_float(f2tf32(vv.x));
            Vs[r * ALD + c4 + 1] = __uint_as_float(f2tf32(vv.y));
            Vs[r * ALD + c4 + 2] = __uint_as_float(f2tf32(vv.z));
            Vs[r * ALD + c4 + 3] = __uint_as_float(f2tf32(vv.w));
        }
        __syncthreads();

        // ---- S = Q K^T : per warp m16 x n64, k=64 ----
        float sacc[8][4];
#pragma unroll
        for (int jn = 0; jn < 8; jn++)
#pragma unroll
            for (int q = 0; q < 4; q++) sacc[jn][q] = 0.0f;

#pragma unroll
        for (int k8 = 0; k8 < 64; k8 += 8) {
            unsigned af[4];
            af[0] = __float_as_uint(Qs[(row_base + g) * ALD + k8 + tig]);
            af[1] = __float_as_uint(Qs[(row_base + g + 8) * ALD + k8 + tig]);
            af[2] = __float_as_uint(Qs[(row_base + g) * ALD + k8 + tig + 4]);
            af[3] = __float_as_uint(Qs[(row_base + g + 8) * ALD + k8 + tig + 4]);
#pragma unroll
            for (int jn = 0; jn < 8; jn++) {
                unsigned bf[2];
                bf[0] = __float_as_uint(Ks[(jn * 8 + g) * ALD + k8 + tig]);
                bf[1] = __float_as_uint(Ks[(jn * 8 + g) * ALD + k8 + tig + 4]);
                mma_m16n8k8(sacc[jn], af, bf);
            }
        }

        // causal mask (only the last two kv tiles can cross the diagonal)
        if (t >= nt - 2) {
#pragma unroll
            for (int jn = 0; jn < 8; jn++)
#pragma unroll
                for (int q = 0; q < 4; q++) {
                    int row = q0 + row_base + g + (q >> 1) * 8;
                    int col = kv0 + jn * 8 + 2 * tig + (q & 1);
                    if (col > row) sacc[jn][q] = NEG_BIG;
                }
        }

        // ---- online softmax (rows g and g+8; 4-lane quad reduction) ----
#pragma unroll
        for (int h = 0; h < 2; h++) {
            float mx = NEG_BIG;
#pragma unroll
            for (int jn = 0; jn < 8; jn++)
                mx = fmaxf(mx, fmaxf(sacc[jn][2 * h], sacc[jn][2 * h + 1]));
            mx = fmaxf(mx, __shfl_xor_sync(0xffffffffu, mx, 1));
            mx = fmaxf(mx, __shfl_xor_sync(0xffffffffu, mx, 2));
            float mn = fmaxf(m_i[h], mx);
            float corr = __expf(m_i[h] - mn);
            m_i[h] = mn;
            float rs = 0.0f;
#pragma unroll
            for (int jn = 0; jn < 8; jn++) {
                float e0 = __expf(sacc[jn][2 * h] - mn);
                float e1 = __expf(sacc[jn][2 * h + 1] - mn);
                sacc[jn][2 * h] = e0;
                sacc[jn][2 * h + 1] = e1;
                rs += e0 + e1;
            }
            rs += __shfl_xor_sync(0xffffffffu, rs, 1);
            rs += __shfl_xor_sync(0xffffffffu, rs, 2);
            l_i[h] = l_i[h] * corr + rs;
#pragma unroll
            for (int jn = 0; jn < 8; jn++) {
                oacc[jn][2 * h] *= corr;
                oacc[jn][2 * h + 1] *= corr;
            }
        }

        // ---- P -> smem (warp-local rows; no block barrier needed) ----
#pragma unroll
        for (int jn = 0; jn < 8; jn++) {
            float2 p0 = make_float2(__uint_as_float(f2tf32(sacc[jn][0])),
                                    __uint_as_float(f2tf32(sacc[jn][1])));
            float2 p1 = make_float2(__uint_as_float(f2tf32(sacc[jn][2])),
                                    __uint_as_float(f2tf32(sacc[jn][3])));
            *(float2*)(Ps + (row_base + g) * ALD + jn * 8 + 2 * tig) = p0;
            *(float2*)(Ps + (row_base + g + 8) * ALD + jn * 8 + 2 * tig) = p1;
        }
        __syncwarp();

        // ---- O += P V : B-frags read V with index swap (V^T[d][j] = Vs[j][d]) ----
#pragma unroll
        for (int k8 = 0; k8 < 64; k8 += 8) {
            unsigned af[4];
            af[0] = __float_as_uint(Ps[(row_base + g) * ALD + k8 + tig]);
            af[1] = __float_as_uint(Ps[(row_base + g + 8) * ALD + k8 + tig]);
            af[2] = __float_as_uint(Ps[(row_base + g) * ALD + k8 + tig + 4]);
            af[3] = __float_as_uint(Ps[(row_base + g + 8) * ALD + k8 + tig + 4]);
#pragma unroll
            for (int jn = 0; jn < 8; jn++) {
                unsigned bf[2];
                bf[0] = __float_as_uint(Vs[(k8 + tig) * ALD + jn * 8 + g]);
                bf[1] = __float_as_uint(Vs[(k8 + tig + 4) * ALD + jn * 8 + g]);
                mma_m16n8k8(oacc[jn], af, bf);
            }
        }
    }

    // ---- epilogue: write O[b, s, h*64+d] ----
    const int b = bh >> 4, h = bh & 15;
#pragma unroll
    for (int hf = 0; hf < 2; hf++) {
        float inv = 1.0f / l_i[hf];
        int s = q0 + row_base + g + hf * 8;
        size_t base = ((size_t)(b * SS + s)) * DD + h * DK;
#pragma unroll
        for (int jn = 0; jn < 8; jn++) {
            float2 v = make_float2(oacc[jn][2 * hf] * inv, oacc[jn][2 * hf + 1] * inv);
            *(float2*)(O + base + jn * 8 + 2 * tig) = v;
        }
    }
}

// ---------------- launch ----------------
extern "C" void kernel_launch(void* const* d_in, const int* in_sizes, int n_in,
                              void* d_out, int out_size) {
    const float* x  = (const float*)d_in[0];
    const float* wq = (const float*)d_in[1];
    const float* wk = (const float*)d_in[2];
    const float* wv = (const float*)d_in[3];
    const float* wo = (const float*)d_in[4];
    float* out = (float*)d_out;

    float *pq, *pk, *pv, *pa;
    cudaGetSymbolAddress((void**)&pq, g_q);
    cudaGetSymbolAddress((void**)&pk, g_k);
    cudaGetSymbolAddress((void**)&pv, g_v);
    cudaGetSymbolAddress((void**)&pa, g_attn);

    static const int attn_smem = (128 + 64 + 64 + 128) * ALD * sizeof(float); // 104448
    cudaFuncSetAttribute(attn_mma, cudaFuncAttributeMaxDynamicSharedMemorySize,
                         attn_smem);

    dim3 gGemm(DD / 128, MM / 128);   // (8, 64)

    gemm_tf32<1><<<gGemm, 256>>>(x, wq, pq);
    gemm_tf32<1><<<gGemm, 256>>>(x, wk, pk);
    gemm_tf32<1><<<gGemm, 256>>>(x, wv, pv);

    dim3 gAttn(SS / 128, BB * HH);    // (16, 64)
    attn_mma<<<gAttn, 256, attn_smem>>>(pq, pk, pv, pa);

    gemm_tf32<0><<<gGemm, 256>>>(pa, wo, out);
}

// round 7
// speedup vs baseline: 2.9277x; 1.0886x over previous
#include <cuda_runtime.h>
#include <cuda_bf16.h>
#include <math.h>

// Problem constants
#define BB 4
#define SS 2048
#define DD 1024
#define HH 16
#define DK 64
#define MM (BB * SS)          // 8192 rows
#define NEG_BIG (-1.0e30f)

// ---------------- scratch (alloc-free: __device__ globals) ----------------
__device__ float g_q[BB * HH * SS * DK];     // [b,h,s,dk]
__device__ float g_k[BB * HH * SS * DK];
__device__ float g_v[BB * HH * SS * DK];
__device__ float g_attn[MM * DD];            // [b*s, h*dk] row-major (tf32-rounded)
__device__ float g_xt[MM * DD];              // tf32-rounded X
__device__ float g_w4[4 * DD * DD];          // tf32-rounded Wq,Wk,Wv,Wo

// ---------------- tf32 helpers ----------------
__device__ __forceinline__ unsigned f2tf32(float f) {
    unsigned r;
    asm("cvt.rna.tf32.f32 %0, %1;" : "=r"(r) : "f"(f));
    return r;
}

__device__ __forceinline__ void mma_m16n8k8(float* d, const unsigned* a,
                                            const unsigned* b) {
    asm volatile(
        "mma.sync.aligned.m16n8k8.row.col.f32.tf32.tf32.f32 "
        "{%0,%1,%2,%3},{%4,%5,%6,%7},{%8,%9},{%0,%1,%2,%3};\n"
        : "+f"(d[0]), "+f"(d[1]), "+f"(d[2]), "+f"(d[3])
        : "r"(a[0]), "r"(a[1]), "r"(a[2]), "r"(a[3]), "r"(b[0]), "r"(b[1]));
}

__device__ __forceinline__ void cp16(void* smem, const void* gmem) {
    unsigned s = (unsigned)__cvta_generic_to_shared(smem);
    asm volatile("cp.async.cg.shared.global [%0], [%1], 16;\n" :: "r"(s), "l"(gmem));
}

// ---------------- pre-pass: tf32-round a float buffer ----------------
__global__ void cvt_tf32_kernel(const float* __restrict__ in,
                                float* __restrict__ out, int n4) {
    int i = blockIdx.x * blockDim.x + threadIdx.x;
    if (i < n4) {
        float4 v = ((const float4*)in)[i];
        v.x = __uint_as_float(f2tf32(v.x));
        v.y = __uint_as_float(f2tf32(v.y));
        v.z = __uint_as_float(f2tf32(v.z));
        v.w = __uint_as_float(f2tf32(v.w));
        ((float4*)out)[i] = v;
    }
}

// ---------------- GEMM: C[M,N] = A[M,K] * W[N,K]^T, tf32 mma + cp.async ----
// A and W must be pre-rounded to tf32. BM=BN=128, BK=16, 2-stage pipeline.
#define GLD 20

template <int SCATTER>
__global__ __launch_bounds__(256, 2) void gemm_tf32(const float* __restrict__ A,
                                                    const float* __restrict__ W,
                                                    float* __restrict__ C) {
    __shared__ float As[2][128][GLD];
    __shared__ float Ws[2][128][GLD];

    const int tid = threadIdx.x;
    const int lane = tid & 31;
    const int wid = tid >> 5;
    const int g = lane >> 2;
    const int tig = lane & 3;
    const int wm0 = (wid >> 2) * 64;
    const int wn0 = (wid & 3) * 32;
    const int row0 = blockIdx.y * 128;
    const int col0 = blockIdx.x * 128;

    // copy-slot geometry: slot0 row r0 = tid>>2, slot1 row r0+64; col group c4
    const int r0 = tid >> 2;
    const int c4 = tid & 3;
    const float* aP0 = A + (size_t)(row0 + r0) * DD + c4 * 4;
    const float* wP0 = W + (size_t)(col0 + r0) * DD + c4 * 4;

    float acc[4][4][4];
#pragma unroll
    for (int im = 0; im < 4; im++)
#pragma unroll
        for (int jn = 0; jn < 4; jn++)
#pragma unroll
            for (int q = 0; q < 4; q++) acc[im][jn][q] = 0.0f;

    // prologue: stage 0
    cp16(&As[0][r0][c4 * 4], aP0);
    cp16(&As[0][r0 + 64][c4 * 4], aP0 + (size_t)64 * DD);
    cp16(&Ws[0][r0][c4 * 4], wP0);
    cp16(&Ws[0][r0 + 64][c4 * 4], wP0 + (size_t)64 * DD);
    asm volatile("cp.async.commit_group;\n");

    const int NK = DD / 16;   // 64
    for (int kt = 0; kt < NK; kt++) {
        const int cur = kt & 1;
        if (kt + 1 < NK) {
            const int nxt = cur ^ 1;
            const int ko = (kt + 1) * 16;
            cp16(&As[nxt][r0][c4 * 4], aP0 + ko);
            cp16(&As[nxt][r0 + 64][c4 * 4], aP0 + (size_t)64 * DD + ko);
            cp16(&Ws[nxt][r0][c4 * 4], wP0 + ko);
            cp16(&Ws[nxt][r0 + 64][c4 * 4], wP0 + (size_t)64 * DD + ko);
            asm volatile("cp.async.commit_group;\n");
            asm volatile("cp.async.wait_group 1;\n");
        } else {
            asm volatile("cp.async.wait_group 0;\n");
        }
        __syncthreads();

#pragma unroll
        for (int k8 = 0; k8 < 16; k8 += 8) {
            unsigned af[4][4], bf[4][2];
#pragma unroll
            for (int im = 0; im < 4; im++) {
                int rb = wm0 + im * 16;
                af[im][0] = __float_as_uint(As[cur][rb + g][k8 + tig]);
                af[im][1] = __float_as_uint(As[cur][rb + g + 8][k8 + tig]);
                af[im][2] = __float_as_uint(As[cur][rb + g][k8 + tig + 4]);
                af[im][3] = __float_as_uint(As[cur][rb + g + 8][k8 + tig + 4]);
            }
#pragma unroll
            for (int jn = 0; jn < 4; jn++) {
                int cb = wn0 + jn * 8;
                bf[jn][0] = __float_as_uint(Ws[cur][cb + g][k8 + tig]);
                bf[jn][1] = __float_as_uint(Ws[cur][cb + g][k8 + tig + 4]);
            }
#pragma unroll
            for (int im = 0; im < 4; im++)
#pragma unroll
                for (int jn = 0; jn < 4; jn++)
                    mma_m16n8k8(acc[im][jn], af[im], bf[jn]);
        }
        __syncthreads();
    }

#pragma unroll
    for (int im = 0; im < 4; im++) {
#pragma unroll
        for (int jn = 0; jn < 4; jn++) {
            int r = row0 + wm0 + im * 16 + g;
            int c = col0 + wn0 + jn * 8 + 2 * tig;
#pragma unroll
            for (int half = 0; half < 2; half++) {
                int rr = r + half * 8;
                float2 v = make_float2(acc[im][jn][half * 2 + 0],
                                       acc[im][jn][half * 2 + 1]);
                if (SCATTER) {
                    int b = rr >> 11;
                    int s = rr & 2047;
                    int h = c >> 6;
                    int d = c & 63;
                    size_t off = (((size_t)(b * HH + h) * SS + s) * DK + d);
                    *(float2*)(C + off) = v;
                } else {
                    *(float2*)(C + (size_t)rr * DD + c) = v;
                }
            }
        }
    }
}

// ---------------- Flash attention (causal) via tf32 mma ----------------
// BM=128, BN=64, dk=64. 256 threads = 8 warps; warp w owns rows [16w,16w+16).
#define ALD 68

__global__ __launch_bounds__(256) void attn_mma(const float* __restrict__ Q,
                                                const float* __restrict__ K,
                                                const float* __restrict__ V,
                                                float* __restrict__ O) {
    extern __shared__ float sm[];
    float* Qs = sm;                    // [128][ALD]
    float* Ks = Qs + 128 * ALD;        // [64][ALD]
    float* Vs = Ks + 64 * ALD;         // [64][ALD]
    float* Ps = Vs + 64 * ALD;         // [128][ALD]

    const int tid = threadIdx.x;
    const int lane = tid & 31;
    const int wid = tid >> 5;
    const int g = lane >> 2;
    const int tig = lane & 3;
    const int qb = (gridDim.x - 1) - blockIdx.x;
    const int bh = blockIdx.y;
    const int q0 = qb * 128;
    const int row_base = wid * 16;

    const float* Qb = Q + (size_t)bh * SS * DK;
    const float* Kb = K + (size_t)bh * SS * DK;
    const float* Vb = V + (size_t)bh * SS * DK;

    for (int idx = tid; idx < 128 * 16; idx += 256) {
        int r = idx >> 4, c4 = (idx & 15) * 4;
        float4 v = *(const float4*)(Qb + (size_t)(q0 + r) * DK + c4);
        Qs[r * ALD + c4 + 0] = __uint_as_float(f2tf32(v.x * 0.125f));
        Qs[r * ALD + c4 + 1] = __uint_as_float(f2tf32(v.y * 0.125f));
        Qs[r * ALD + c4 + 2] = __uint_as_float(f2tf32(v.z * 0.125f));
        Qs[r * ALD + c4 + 3] = __uint_as_float(f2tf32(v.w * 0.125f));
    }

    float m_i[2] = {NEG_BIG, NEG_BIG};
    float l_i[2] = {0.0f, 0.0f};
    float oacc[8][4];
#pragma unroll
    for (int jn = 0; jn < 8; jn++)
#pragma unroll
        for (int q = 0; q < 4; q++) oacc[jn][q] = 0.0f;

    const int nt = 2 * qb + 2;
    for (int t = 0; t < nt; t++) {
        const int kv0 = t * 64;
        __syncthreads();
        for (int idx = tid; idx < 64 * 16; idx += 256) {
            int r = idx >> 4, c4 = (idx & 15) * 4;
            float4 kv = *(const float4*)(Kb + (size_t)(kv0 + r) * DK + c4);
            float4 vv = *(const float4*)(Vb + (size_t)(kv0 + r) * DK + c4);
            Ks[r * ALD + c4 + 0] = __uint_as_float(f2tf32(kv.x));
            Ks[r * ALD + c4 + 1] = __uint_as_float(f2tf32(kv.y));
            Ks[r * ALD + c4 + 2] = __uint_as_float(f2tf32(kv.z));
            Ks[r * ALD + c4 + 3] = __uint_as_float(f2tf32(kv.w));
            Vs[r * ALD + c4 + 0] = __uint_as_float(f2tf32(vv.x));
            Vs[r * ALD + c4 + 1] = __uint_as_float(f2tf32(vv.y));
            Vs[r * ALD + c4 + 2] = __uint_as_float(f2tf32(vv.z));
            Vs[r * ALD + c4 + 3] = __uint_as_float(f2tf32(vv.w));
        }
        __syncthreads();

        float sacc[8][4];
#pragma unroll
        for (int jn = 0; jn < 8; jn++)
#pragma unroll
            for (int q = 0; q < 4; q++) sacc[jn][q] = 0.0f;

#pragma unroll
        for (int k8 = 0; k8 < 64; k8 += 8) {
            unsigned af[4];
            af[0] = __float_as_uint(Qs[(row_base + g) * ALD + k8 + tig]);
            af[1] = __float_as_uint(Qs[(row_base + g + 8) * ALD + k8 + tig]);
            af[2] = __float_as_uint(Qs[(row_base + g) * ALD + k8 + tig + 4]);
            af[3] = __float_as_uint(Qs[(row_base + g + 8) * ALD + k8 + tig + 4]);
#pragma unroll
            for (int jn = 0; jn < 8; jn++) {
                unsigned bf[2];
                bf[0] = __float_as_uint(Ks[(jn * 8 + g) * ALD + k8 + tig]);
                bf[1] = __float_as_uint(Ks[(jn * 8 + g) * ALD + k8 + tig + 4]);
                mma_m16n8k8(sacc[jn], af, bf);
            }
        }

        if (t >= nt - 2) {
#pragma unroll
            for (int jn = 0; jn < 8; jn++)
#pragma unroll
                for (int q = 0; q < 4; q++) {
                    int row = q0 + row_base + g + (q >> 1) * 8;
                    int col = kv0 + jn * 8 + 2 * tig + (q & 1);
                    if (col > row) sacc[jn][q] = NEG_BIG;
                }
        }

#pragma unroll
        for (int h = 0; h < 2; h++) {
            float mx = NEG_BIG;
#pragma unroll
            for (int jn = 0; jn < 8; jn++)
                mx = fmaxf(mx, fmaxf(sacc[jn][2 * h], sacc[jn][2 * h + 1]));
            mx = fmaxf(mx, __shfl_xor_sync(0xffffffffu, mx, 1));
            mx = fmaxf(mx, __shfl_xor_sync(0xffffffffu, mx, 2));
            float mn = fmaxf(m_i[h], mx);
            float corr = __expf(m_i[h] - mn);
            m_i[h] = mn;
            float rs = 0.0f;
#pragma unroll
            for (int jn = 0; jn < 8; jn++) {
                float e0 = __expf(sacc[jn][2 * h] - mn);
                float e1 = __expf(sacc[jn][2 * h + 1] - mn);
                sacc[jn][2 * h] = e0;
                sacc[jn][2 * h + 1] = e1;
                rs += e0 + e1;
            }
            rs += __shfl_xor_sync(0xffffffffu, rs, 1);
            rs += __shfl_xor_sync(0xffffffffu, rs, 2);
            l_i[h] = l_i[h] * corr + rs;
#pragma unroll
            for (int jn = 0; jn < 8; jn++) {
                oacc[jn][2 * h] *= corr;
                oacc[jn][2 * h + 1] *= corr;
            }
        }

#pragma unroll
        for (int jn = 0; jn < 8; jn++) {
            float2 p0 = make_float2(__uint_as_float(f2tf32(sacc[jn][0])),
                                    __uint_as_float(f2tf32(sacc[jn][1])));
            float2 p1 = make_float2(__uint_as_float(f2tf32(sacc[jn][2])),
                                    __uint_as_float(f2tf32(sacc[jn][3])));
            *(float2*)(Ps + (row_base + g) * ALD + jn * 8 + 2 * tig) = p0;
            *(float2*)(Ps + (row_base + g + 8) * ALD + jn * 8 + 2 * tig) = p1;
        }
        __syncwarp();

#pragma unroll
        for (int k8 = 0; k8 < 64; k8 += 8) {
            unsigned af[4];
            af[0] = __float_as_uint(Ps[(row_base + g) * ALD + k8 + tig]);
            af[1] = __float_as_uint(Ps[(row_base + g + 8) * ALD + k8 + tig]);
            af[2] = __float_as_uint(Ps[(row_base + g) * ALD + k8 + tig + 4]);
            af[3] = __float_as_uint(Ps[(row_base + g + 8) * ALD + k8 + tig + 4]);
#pragma unroll
            for (int jn = 0; jn < 8; jn++) {
                unsigned bf[2];
                bf[0] = __float_as_uint(Vs[(k8 + tig) * ALD + jn * 8 + g]);
                bf[1] = __float_as_uint(Vs[(k8 + tig + 4) * ALD + jn * 8 + g]);
                mma_m16n8k8(oacc[jn], af, bf);
            }
        }
    }

    // epilogue: write O[b, s, h*64+d], tf32-rounded (feeds final GEMM directly)
    const int b = bh >> 4, h = bh & 15;
#pragma unroll
    for (int hf = 0; hf < 2; hf++) {
        float inv = 1.0f / l_i[hf];
        int s = q0 + row_base + g + hf * 8;
        size_t base = ((size_t)(b * SS + s)) * DD + h * DK;
#pragma unroll
        for (int jn = 0; jn < 8; jn++) {
            float2 v = make_float2(
                __uint_as_float(f2tf32(oacc[jn][2 * hf] * inv)),
                __uint_as_float(f2tf32(oacc[jn][2 * hf + 1] * inv)));
            *(float2*)(O + base + jn * 8 + 2 * tig) = v;
        }
    }
}

// ---------------- launch ----------------
extern "C" void kernel_launch(void* const* d_in, const int* in_sizes, int n_in,
                              void* d_out, int out_size) {
    const float* x  = (const float*)d_in[0];
    const float* wq = (const float*)d_in[1];
    const float* wk = (const float*)d_in[2];
    const float* wv = (const float*)d_in[3];
    const float* wo = (const float*)d_in[4];
    float* out = (float*)d_out;

    float *pq, *pk, *pv, *pa, *pxt, *pw4;
    cudaGetSymbolAddress((void**)&pq, g_q);
    cudaGetSymbolAddress((void**)&pk, g_k);
    cudaGetSymbolAddress((void**)&pv, g_v);
    cudaGetSymbolAddress((void**)&pa, g_attn);
    cudaGetSymbolAddress((void**)&pxt, g_xt);
    cudaGetSymbolAddress((void**)&pw4, g_w4);

    static const int attn_smem = (128 + 64 + 64 + 128) * ALD * sizeof(float); // 104448
    cudaFuncSetAttribute(attn_mma, cudaFuncAttributeMaxDynamicSharedMemorySize,
                         attn_smem);

    // pre-pass: tf32-round X and weights
    const int n4x = MM * DD / 4;         // 2M
    const int n4w = DD * DD / 4;         // 256K
    cvt_tf32_kernel<<<(n4x + 255) / 256, 256>>>(x, pxt, n4x);
    cvt_tf32_kernel<<<(n4w + 255) / 256, 256>>>(wq, pw4 + 0 * DD * DD, n4w);
    cvt_tf32_kernel<<<(n4w + 255) / 256, 256>>>(wk, pw4 + 1 * DD * DD, n4w);
    cvt_tf32_kernel<<<(n4w + 255) / 256, 256>>>(wv, pw4 + 2 * DD * DD, n4w);
    cvt_tf32_kernel<<<(n4w + 255) / 256, 256>>>(wo, pw4 + 3 * DD * DD, n4w);

    dim3 gGemm(DD / 128, MM / 128);   // (8, 64)

    gemm_tf32<1><<<gGemm, 256>>>(pxt, pw4 + 0 * DD * DD, pq);
    gemm_tf32<1><<<gGemm, 256>>>(pxt, pw4 + 1 * DD * DD, pk);
    gemm_tf32<1><<<gGemm, 256>>>(pxt, pw4 + 2 * DD * DD, pv);

    dim3 gAttn(SS / 128, BB * HH);    // (16, 64)
    attn_mma<<<gAttn, 256, attn_smem>>>(pq, pk, pv, pa);

    gemm_tf32<0><<<gGemm, 256>>>(pa, pw4 + 3 * DD * DD, out);
}

// round 8
// speedup vs baseline: 3.0518x; 1.0424x over previous
#include <cuda_runtime.h>
#include <cuda_bf16.h>
#include <math.h>

// Problem constants
#define BB 4
#define SS 2048
#define DD 1024
#define HH 16
#define DK 64
#define MM (BB * SS)          // 8192 rows
#define NEG_BIG (-1.0e30f)

// ---------------- scratch (alloc-free: __device__ globals) ----------------
__device__ float g_q[BB * HH * SS * DK];     // [b,h,s,dk]
__device__ float g_k[BB * HH * SS * DK];
__device__ float g_v[BB * HH * SS * DK];
__device__ float g_attn[MM * DD];            // [b*s, h*dk] (tf32-rounded)
__device__ float g_xt[MM * DD];              // tf32-rounded X
__device__ float g_w4[4 * DD * DD];          // tf32-rounded Wq,Wk,Wv,Wo

// ---------------- tf32 helpers ----------------
__device__ __forceinline__ unsigned f2tf32(float f) {
    unsigned r;
    asm("cvt.rna.tf32.f32 %0, %1;" : "=r"(r) : "f"(f));
    return r;
}

__device__ __forceinline__ void mma_m16n8k8(float* d, const unsigned* a,
                                            const unsigned* b) {
    asm volatile(
        "mma.sync.aligned.m16n8k8.row.col.f32.tf32.tf32.f32 "
        "{%0,%1,%2,%3},{%4,%5,%6,%7},{%8,%9},{%0,%1,%2,%3};\n"
        : "+f"(d[0]), "+f"(d[1]), "+f"(d[2]), "+f"(d[3])
        : "r"(a[0]), "r"(a[1]), "r"(a[2]), "r"(a[3]), "r"(b[0]), "r"(b[1]));
}

__device__ __forceinline__ void cp16(void* smem, const void* gmem) {
    unsigned s = (unsigned)__cvta_generic_to_shared(smem);
    asm volatile("cp.async.cg.shared.global [%0], [%1], 16;\n" :: "r"(s), "l"(gmem));
}

// ---------------- pre-pass kernels ----------------
__global__ void cvt_tf32_kernel(const float* __restrict__ in,
                                float* __restrict__ out, int n4) {
    int i = blockIdx.x * blockDim.x + threadIdx.x;
    if (i < n4) {
        float4 v = ((const float4*)in)[i];
        v.x = __uint_as_float(f2tf32(v.x));
        v.y = __uint_as_float(f2tf32(v.y));
        v.z = __uint_as_float(f2tf32(v.z));
        v.w = __uint_as_float(f2tf32(v.w));
        ((float4*)out)[i] = v;
    }
}

__global__ void cvt_tf32_w4_kernel(const float* __restrict__ w0,
                                   const float* __restrict__ w1,
                                   const float* __restrict__ w2,
                                   const float* __restrict__ w3,
                                   float* __restrict__ out) {
    const int n4w = DD * DD / 4;
    int i = blockIdx.x * blockDim.x + threadIdx.x;
    if (i < 4 * n4w) {
        int w = i / n4w, j = i - w * n4w;
        const float* src = (w == 0) ? w0 : (w == 1) ? w1 : (w == 2) ? w2 : w3;
        float4 v = ((const float4*)src)[j];
        v.x = __uint_as_float(f2tf32(v.x));
        v.y = __uint_as_float(f2tf32(v.y));
        v.z = __uint_as_float(f2tf32(v.z));
        v.w = __uint_as_float(f2tf32(v.w));
        ((float4*)(out + (size_t)w * DD * DD))[j] = v;
    }
}

// ---------------- GEMM: C[M,N] = A[M,K] * W[N,K]^T, tf32 mma, 4-stage cp.async
#define GLD 20
#define GSTG 4

template <int SCATTER>
__global__ __launch_bounds__(256, 2) void gemm_tf32(const float* __restrict__ A,
                                                    const float* __restrict__ W,
                                                    float* __restrict__ C) {
    extern __shared__ float gsm[];
    float (*As)[128][GLD] = (float (*)[128][GLD])gsm;
    float (*Ws)[128][GLD] = (float (*)[128][GLD])(gsm + GSTG * 128 * GLD);

    const int tid = threadIdx.x;
    const int lane = tid & 31;
    const int wid = tid >> 5;
    const int g = lane >> 2;
    const int tig = lane & 3;
    const int wm0 = (wid >> 2) * 64;
    const int wn0 = (wid & 3) * 32;
    const int row0 = blockIdx.y * 128;
    const int col0 = blockIdx.x * 128;

    const int r0 = tid >> 2;
    const int c4 = tid & 3;
    const float* aP0 = A + (size_t)(row0 + r0) * DD + c4 * 4;
    const float* wP0 = W + (size_t)(col0 + r0) * DD + c4 * 4;

    float acc[4][4][4];
#pragma unroll
    for (int im = 0; im < 4; im++)
#pragma unroll
        for (int jn = 0; jn < 4; jn++)
#pragma unroll
            for (int q = 0; q < 4; q++) acc[im][jn][q] = 0.0f;

    const int NK = DD / 16;   // 64
    // prologue: stages 0..2
#pragma unroll
    for (int s = 0; s < 3; s++) {
        const int ko = s * 16;
        cp16(&As[s][r0][c4 * 4], aP0 + ko);
        cp16(&As[s][r0 + 64][c4 * 4], aP0 + (size_t)64 * DD + ko);
        cp16(&Ws[s][r0][c4 * 4], wP0 + ko);
        cp16(&Ws[s][r0 + 64][c4 * 4], wP0 + (size_t)64 * DD + ko);
        asm volatile("cp.async.commit_group;\n");
    }

    for (int kt = 0; kt < NK; kt++) {
        // wait until stage kt is resident
        if (kt < NK - 2)      asm volatile("cp.async.wait_group 2;\n");
        else if (kt == NK - 2) asm volatile("cp.async.wait_group 1;\n");
        else                  asm volatile("cp.async.wait_group 0;\n");
        __syncthreads();      // also fences compute of stage kt-1 (buffer (kt+3)%4)

        if (kt + 3 < NK) {
            const int nxt = (kt + 3) & 3;
            const int ko = (kt + 3) * 16;
            cp16(&As[nxt][r0][c4 * 4], aP0 + ko);
            cp16(&As[nxt][r0 + 64][c4 * 4], aP0 + (size_t)64 * DD + ko);
            cp16(&Ws[nxt][r0][c4 * 4], wP0 + ko);
            cp16(&Ws[nxt][r0 + 64][c4 * 4], wP0 + (size_t)64 * DD + ko);
            asm volatile("cp.async.commit_group;\n");
        }

        const int cur = kt & 3;
#pragma unroll
        for (int k8 = 0; k8 < 16; k8 += 8) {
            unsigned af[4][4], bf[4][2];
#pragma unroll
            for (int im = 0; im < 4; im++) {
                int rb = wm0 + im * 16;
                af[im][0] = __float_as_uint(As[cur][rb + g][k8 + tig]);
                af[im][1] = __float_as_uint(As[cur][rb + g + 8][k8 + tig]);
                af[im][2] = __float_as_uint(As[cur][rb + g][k8 + tig + 4]);
                af[im][3] = __float_as_uint(As[cur][rb + g + 8][k8 + tig + 4]);
            }
#pragma unroll
            for (int jn = 0; jn < 4; jn++) {
                int cb = wn0 + jn * 8;
                bf[jn][0] = __float_as_uint(Ws[cur][cb + g][k8 + tig]);
                bf[jn][1] = __float_as_uint(Ws[cur][cb + g][k8 + tig + 4]);
            }
#pragma unroll
            for (int im = 0; im < 4; im++)
#pragma unroll
                for (int jn = 0; jn < 4; jn++)
                    mma_m16n8k8(acc[im][jn], af[im], bf[jn]);
        }
    }

#pragma unroll
    for (int im = 0; im < 4; im++) {
#pragma unroll
        for (int jn = 0; jn < 4; jn++) {
            int r = row0 + wm0 + im * 16 + g;
            int c = col0 + wn0 + jn * 8 + 2 * tig;
#pragma unroll
            for (int half = 0; half < 2; half++) {
                int rr = r + half * 8;
                float2 v = make_float2(acc[im][jn][half * 2 + 0],
                                       acc[im][jn][half * 2 + 1]);
                if (SCATTER) {
                    int b = rr >> 11;
                    int s = rr & 2047;
                    int h = c >> 6;
                    int d = c & 63;
                    size_t off = (((size_t)(b * HH + h) * SS + s) * DK + d);
                    *(float2*)(C + off) = v;
                } else {
                    *(float2*)(C + (size_t)rr * DD + c) = v;
                }
            }
        }
    }
}

// ---------------- Flash attention (causal) via tf32 mma ----------------
// BM=128, BN=64. 8 warps; warp w owns rows [16w,16w+16).
// Q fragments live in registers; the Q smem buffer is reused for P.
// smem = (128+64+64)*ALD*4 = 69632 B -> 2 CTAs/SM.
#define ALD 68

__global__ __launch_bounds__(256, 2) void attn_mma(const float* __restrict__ Q,
                                                   const float* __restrict__ K,
                                                   const float* __restrict__ V,
                                                   float* __restrict__ O) {
    extern __shared__ float sm[];
    float* Ps = sm;                    // [128][ALD]  (first holds Q, then P)
    float* Ks = Ps + 128 * ALD;        // [64][ALD]
    float* Vs = Ks + 64 * ALD;         // [64][ALD]

    const int tid = threadIdx.x;
    const int lane = tid & 31;
    const int wid = tid >> 5;
    const int g = lane >> 2;
    const int tig = lane & 3;
    const int qb = (gridDim.x - 1) - blockIdx.x;
    const int bh = blockIdx.y;
    const int q0 = qb * 128;
    const int row_base = wid * 16;

    const float* Qb = Q + (size_t)bh * SS * DK;
    const float* Kb = K + (size_t)bh * SS * DK;
    const float* Vb = V + (size_t)bh * SS * DK;

    // warp-local Q load: warp w loads its own rows [16w,16w+16) (scaled, tf32)
#pragma unroll
    for (int i = 0; i < 8; i++) {
        int idx = lane + 32 * i;            // 0..255
        int r = row_base + (idx >> 4);
        int c4 = (idx & 15) * 4;
        float4 v = *(const float4*)(Qb + (size_t)(q0 + r) * DK + c4);
        Ps[r * ALD + c4 + 0] = __uint_as_float(f2tf32(v.x * 0.125f));
        Ps[r * ALD + c4 + 1] = __uint_as_float(f2tf32(v.y * 0.125f));
        Ps[r * ALD + c4 + 2] = __uint_as_float(f2tf32(v.z * 0.125f));
        Ps[r * ALD + c4 + 3] = __uint_as_float(f2tf32(v.w * 0.125f));
    }
    __syncwarp();

    // hoist Q fragments to registers (8 k8-steps x 4 regs)
    unsigned qf[8][4];
#pragma unroll
    for (int s = 0; s < 8; s++) {
        int k8 = s * 8;
        qf[s][0] = __float_as_uint(Ps[(row_base + g) * ALD + k8 + tig]);
        qf[s][1] = __float_as_uint(Ps[(row_base + g + 8) * ALD + k8 + tig]);
        qf[s][2] = __float_as_uint(Ps[(row_base + g) * ALD + k8 + tig + 4]);
        qf[s][3] = __float_as_uint(Ps[(row_base + g + 8) * ALD + k8 + tig + 4]);
    }
    __syncwarp();   // Q reads done; Ps rows may now be overwritten (warp-local)

    float m_i[2] = {NEG_BIG, NEG_BIG};
    float l_i[2] = {0.0f, 0.0f};
    float oacc[8][4];
#pragma unroll
    for (int jn = 0; jn < 8; jn++)
#pragma unroll
        for (int q = 0; q < 4; q++) oacc[jn][q] = 0.0f;

    const int nt = 2 * qb + 2;
    for (int t = 0; t < nt; t++) {
        const int kv0 = t * 64;
        __syncthreads();
        for (int idx = tid; idx < 64 * 16; idx += 256) {
            int r = idx >> 4, c4 = (idx & 15) * 4;
            float4 kv = *(const float4*)(Kb + (size_t)(kv0 + r) * DK + c4);
            float4 vv = *(const float4*)(Vb + (size_t)(kv0 + r) * DK + c4);
            Ks[r * ALD + c4 + 0] = __uint_as_float(f2tf32(kv.x));
            Ks[r * ALD + c4 + 1] = __uint_as_float(f2tf32(kv.y));
            Ks[r * ALD + c4 + 2] = __uint_as_float(f2tf32(kv.z));
            Ks[r * ALD + c4 + 3] = __uint_as_float(f2tf32(kv.w));
            Vs[r * ALD + c4 + 0] = __uint_as_float(f2tf32(vv.x));
            Vs[r * ALD + c4 + 1] = __uint_as_float(f2tf32(vv.y));
            Vs[r * ALD + c4 + 2] = __uint_as_float(f2tf32(vv.z));
            Vs[r * ALD + c4 + 3] = __uint_as_float(f2tf32(vv.w));
        }
        __syncthreads();

        // ---- S = Q K^T ----
        float sacc[8][4];
#pragma unroll
        for (int jn = 0; jn < 8; jn++)
#pragma unroll
            for (int q = 0; q < 4; q++) sacc[jn][q] = 0.0f;

#pragma unroll
        for (int s = 0; s < 8; s++) {
            int k8 = s * 8;
#pragma unroll
            for (int jn = 0; jn < 8; jn++) {
                unsigned bf[2];
                bf[0] = __float_as_uint(Ks[(jn * 8 + g) * ALD + k8 + tig]);
                bf[1] = __float_as_uint(Ks[(jn * 8 + g) * ALD + k8 + tig + 4]);
                mma_m16n8k8(sacc[jn], qf[s], bf);
            }
        }

        if (t >= nt - 2) {
#pragma unroll
            for (int jn = 0; jn < 8; jn++)
#pragma unroll
                for (int q = 0; q < 4; q++) {
                    int row = q0 + row_base + g + (q >> 1) * 8;
                    int col = kv0 + jn * 8 + 2 * tig + (q & 1);
                    if (col > row) sacc[jn][q] = NEG_BIG;
                }
        }

        // ---- online softmax ----
#pragma unroll
        for (int h = 0; h < 2; h++) {
            float mx = NEG_BIG;
#pragma unroll
            for (int jn = 0; jn < 8; jn++)
                mx = fmaxf(mx, fmaxf(sacc[jn][2 * h], sacc[jn][2 * h + 1]));
            mx = fmaxf(mx, __shfl_xor_sync(0xffffffffu, mx, 1));
            mx = fmaxf(mx, __shfl_xor_sync(0xffffffffu, mx, 2));
            float mn = fmaxf(m_i[h], mx);
            float corr = __expf(m_i[h] - mn);
            m_i[h] = mn;
            float rs = 0.0f;
#pragma unroll
            for (int jn = 0; jn < 8; jn++) {
                float e0 = __expf(sacc[jn][2 * h] - mn);
                float e1 = __expf(sacc[jn][2 * h + 1] - mn);
                sacc[jn][2 * h] = e0;
                sacc[jn][2 * h + 1] = e1;
                rs += e0 + e1;
            }
            rs += __shfl_xor_sync(0xffffffffu, rs, 1);
            rs += __shfl_xor_sync(0xffffffffu, rs, 2);
            l_i[h] = l_i[h] * corr + rs;
#pragma unroll
            for (int jn = 0; jn < 8; jn++) {
                oacc[jn][2 * h] *= corr;
                oacc[jn][2 * h + 1] *= corr;
            }
        }

        // ---- P -> smem (warp-local rows) ----
#pragma unroll
        for (int jn = 0; jn < 8; jn++) {
            float2 p0 = make_float2(__uint_as_float(f2tf32(sacc[jn][0])),
                                    __uint_as_float(f2tf32(sacc[jn][1])));
            float2 p1 = make_float2(__uint_as_float(f2tf32(sacc[jn][2])),
                                    __uint_as_float(f2tf32(sacc[jn][3])));
            *(float2*)(Ps + (row_base + g) * ALD + jn * 8 + 2 * tig) = p0;
            *(float2*)(Ps + (row_base + g + 8) * ALD + jn * 8 + 2 * tig) = p1;
        }
        __syncwarp();

        // ---- O += P V ----
#pragma unroll
        for (int s = 0; s < 8; s++) {
            int k8 = s * 8;
            unsigned af[4];
            af[0] = __float_as_uint(Ps[(row_base + g) * ALD + k8 + tig]);
            af[1] = __float_as_uint(Ps[(row_base + g + 8) * ALD + k8 + tig]);
            af[2] = __float_as_uint(Ps[(row_base + g) * ALD + k8 + tig + 4]);
            af[3] = __float_as_uint(Ps[(row_base + g + 8) * ALD + k8 + tig + 4]);
#pragma unroll
            for (int jn = 0; jn < 8; jn++) {
                unsigned bf[2];
                bf[0] = __float_as_uint(Vs[(k8 + tig) * ALD + jn * 8 + g]);
                bf[1] = __float_as_uint(Vs[(k8 + tig + 4) * ALD + jn * 8 + g]);
                mma_m16n8k8(oacc[jn], af, bf);
            }
        }
        __syncwarp();   // PV reads of Ps done before next iteration's P write
    }

    // epilogue: write O[b, s, h*64+d], tf32-rounded (feeds final GEMM)
    const int b = bh >> 4, h = bh & 15;
#pragma unroll
    for (int hf = 0; hf < 2; hf++) {
        float inv = 1.0f / l_i[hf];
        int s = q0 + row_base + g + hf * 8;
        size_t base = ((size_t)(b * SS + s)) * DD + h * DK;
#pragma unroll
        for (int jn = 0; jn < 8; jn++) {
            float2 v = make_float2(
                __uint_as_float(f2tf32(oacc[jn][2 * hf] * inv)),
                __uint_as_float(f2tf32(oacc[jn][2 * hf + 1] * inv)));
            *(float2*)(O + base + jn * 8 + 2 * tig) = v;
        }
    }
}

// ---------------- launch ----------------
extern "C" void kernel_launch(void* const* d_in, const int* in_sizes, int n_in,
                              void* d_out, int out_size) {
    const float* x  = (const float*)d_in[0];
    const float* wq = (const float*)d_in[1];
    const float* wk = (const float*)d_in[2];
    const float* wv = (const float*)d_in[3];
    const float* wo = (const float*)d_in[4];
    float* out = (float*)d_out;

    float *pq, *pk, *pv, *pa, *pxt, *pw4;
    cudaGetSymbolAddress((void**)&pq, g_q);
    cudaGetSymbolAddress((void**)&pk, g_k);
    cudaGetSymbolAddress((void**)&pv, g_v);
    cudaGetSymbolAddress((void**)&pa, g_attn);
    cudaGetSymbolAddress((void**)&pxt, g_xt);
    cudaGetSymbolAddress((void**)&pw4, g_w4);

    static const int attn_smem = (128 + 64 + 64) * ALD * sizeof(float);  // 69632
    static const int gemm_smem = 2 * GSTG * 128 * GLD * sizeof(float);   // 81920
    cudaFuncSetAttribute(attn_mma, cudaFuncAttributeMaxDynamicSharedMemorySize,
                         attn_smem);
    cudaFuncSetAttribute(gemm_tf32<0>, cudaFuncAttributeMaxDynamicSharedMemorySize,
                         gemm_smem);
    cudaFuncSetAttribute(gemm_tf32<1>, cudaFuncAttributeMaxDynamicSharedMemorySize,
                         gemm_smem);

    // pre-pass: tf32-round X and weights
    const int n4x = MM * DD / 4;
    const int n4w4 = 4 * DD * DD / 4;
    cvt_tf32_kernel<<<(n4x + 255) / 256, 256>>>(x, pxt, n4x);
    cvt_tf32_w4_kernel<<<(n4w4 + 255) / 256, 256>>>(wq, wk, wv, wo, pw4);

    dim3 gGemm(DD / 128, MM / 128);   // (8, 64)

    gemm_tf32<1><<<gGemm, 256, gemm_smem>>>(pxt, pw4 + 0 * DD * DD, pq);
    gemm_tf32<1><<<gGemm, 256, gemm_smem>>>(pxt, pw4 + 1 * DD * DD, pk);
    gemm_tf32<1><<<gGemm, 256, gemm_smem>>>(pxt, pw4 + 2 * DD * DD, pv);

    dim3 gAttn(SS / 128, BB * HH);    // (16, 64)
    attn_mma<<<gAttn, 256, attn_smem>>>(pq, pk, pv, pa);

    gemm_tf32<0><<<gGemm, 256, gemm_smem>>>(pa, pw4 + 3 * DD * DD, out);
}

// round 9
// speedup vs baseline: 3.7340x; 1.2236x over previous
#include <cuda_runtime.h>
#include <cuda_bf16.h>
#include <math.h>

// Problem constants
#define BB 4
#define SS 2048
#define DD 1024
#define HH 16
#define DK 64
#define MM (BB * SS)          // 8192 rows
#define NEG_BIG (-1.0e30f)

// ---------------- scratch (alloc-free: __device__ globals) ----------------
__device__ float g_q[BB * HH * SS * DK];     // [b,h,s,dk]
__device__ float g_k[BB * HH * SS * DK];
__device__ float g_v[BB * HH * SS * DK];
__device__ float g_attn[MM * DD];            // packed-A layout (tf32)
__device__ float g_xt[MM * DD];              // packed-A layout (tf32)
__device__ float g_w4[4 * DD * DD];          // packed-B layout (tf32) Wq,Wk,Wv,Wo

// ---------------- tf32 helpers ----------------
__device__ __forceinline__ unsigned f2tf32(float f) {
    unsigned r;
    asm("cvt.rna.tf32.f32 %0, %1;" : "=r"(r) : "f"(f));
    return r;
}
__device__ __forceinline__ float f2tf32f(float f) {
    return __uint_as_float(f2tf32(f));
}

__device__ __forceinline__ void mma_m16n8k8(float* d, const unsigned* a,
                                            const unsigned* b) {
    asm volatile(
        "mma.sync.aligned.m16n8k8.row.col.f32.tf32.tf32.f32 "
        "{%0,%1,%2,%3},{%4,%5,%6,%7},{%8,%9},{%0,%1,%2,%3};\n"
        : "+f"(d[0]), "+f"(d[1]), "+f"(d[2]), "+f"(d[3])
        : "r"(a[0]), "r"(a[1]), "r"(a[2]), "r"(a[3]), "r"(b[0]), "r"(b[1]));
}

__device__ __forceinline__ void cp16(void* smem, const void* gmem) {
    unsigned s = (unsigned)__cvta_generic_to_shared(smem);
    asm volatile("cp.async.cg.shared.global [%0], [%1], 16;\n" :: "r"(s), "l"(gmem));
}

// packed-A address: element (r, c) of an M x 1024 matrix
// tile (tm=r/16, tk=c/8); lane = (r%8)*4 + (c%4); v = ((r%16)/8) + 2*((c%8)/4)
__device__ __forceinline__ size_t packA_addr(int r, int c) {
    return ((size_t)((r >> 4) * 128 + (c >> 3)) << 7) +
           ((r & 7) * 16 + (c & 3) * 4 + ((r >> 3) & 1) + 2 * ((c >> 2) & 1));
}

// ---------------- pre-pass: pack X (A layout) ----------------
// out float4 index i: tm = i>>12, tk = (i>>5)&127, lane = i&31
__global__ void pack_a_kernel(const float* __restrict__ A, float* __restrict__ out,
                              int n4) {
    int i = blockIdx.x * blockDim.x + threadIdx.x;
    if (i >= n4) return;
    int tm = i >> 12;
    int tk = (i >> 5) & 127;
    int lane = i & 31;
    int g = lane >> 2, tig = lane & 3;
    int r0 = tm * 16, c0 = tk * 8;
    const float* p = A + (size_t)r0 * DD + c0;
    float4 v;
    v.x = f2tf32f(p[(size_t)g * DD + tig]);
    v.y = f2tf32f(p[(size_t)(g + 8) * DD + tig]);
    v.z = f2tf32f(p[(size_t)g * DD + tig + 4]);
    v.w = f2tf32f(p[(size_t)(g + 8) * DD + tig + 4]);
    ((float4*)out)[i] = v;
}

// ---------------- pre-pass: pack 4 weights (B layout) ----------------
// per weight: out float4 index i: tn = i>>12 (64), tk = (i>>5)&127, lane = i&31
// v order: v0 = (n=g,   k=tig), v1 = (n=g,   k=tig+4),
//          v2 = (n=g+8, k=tig), v3 = (n=g+8, k=tig+4)
__global__ void pack_w4_kernel(const float* __restrict__ w0,
                               const float* __restrict__ w1,
                               const float* __restrict__ w2,
                               const float* __restrict__ w3,
                               float* __restrict__ out) {
    const int per_w = DD * DD / 4;   // 262144 float4
    int j = blockIdx.x * blockDim.x + threadIdx.x;
    if (j >= 4 * per_w) return;
    int w = j / per_w, i = j - w * per_w;
    const float* W = (w == 0) ? w0 : (w == 1) ? w1 : (w == 2) ? w2 : w3;
    int tn = i >> 12;
    int tk = (i >> 5) & 127;
    int lane = i & 31;
    int g = lane >> 2, tig = lane & 3;
    int n0 = tn * 16, k0 = tk * 8;
    const float* p = W + (size_t)n0 * DD + k0;
    float4 v;
    v.x = f2tf32f(p[(size_t)g * DD + tig]);
    v.y = f2tf32f(p[(size_t)g * DD + tig + 4]);
    v.z = f2tf32f(p[(size_t)(g + 8) * DD + tig]);
    v.w = f2tf32f(p[(size_t)(g + 8) * DD + tig + 4]);
    ((float4*)(out + (size_t)w * DD * DD))[j - w * per_w] = v;
}

// ---------------- GEMM core: packed A [M,1024] x packed B -> C ----------------
// BM=BN=128, BK=16, 4-stage cp.async. 8 warps, warp tile 64x32.
// MODE 0: C row-major [M, 1024] (out projection)
// MODE 1: QKV scatter: col_global < 3072; w=col>>10 selects q/k/v buffer,
//         written as [b,h,s,dk].
#define GSTG 4
#define STGF 2048          // floats per stage per operand (128x16)

template <int MODE>
__global__ __launch_bounds__(256, 2) void gemm_pk(const float* __restrict__ A,
                                                  const float* __restrict__ W,
                                                  float* __restrict__ C0,
                                                  float* __restrict__ C1,
                                                  float* __restrict__ C2) {
    extern __shared__ float gsm[];
    float* As = gsm;                         // [GSTG][8][2][128]
    float* Bs = gsm + GSTG * STGF;           // [GSTG][8][2][128]

    const int tid = threadIdx.x;
    const int lane = tid & 31;
    const int wid = tid >> 5;
    const int g = lane >> 2;
    const int tig = lane & 3;
    const int wm0 = (wid >> 2) * 64;         // 0 or 64
    const int wn0 = (wid & 3) * 32;          // 0,32,64,96
    const int row0 = blockIdx.y * 128;
    const int col0 = blockIdx.x * 128;

    // cp.async geometry: 512 chunks of 16B per operand per stage; 2 per thread
    // q: tm_l = q>>6, tk_l = (q>>5)&1, f4 = q&31
    const float* Abase = A + (size_t)(row0 >> 4) * 16384;
    const float* Wbase = W + (size_t)(col0 >> 4) * 16384;

    float acc[4][4][4];
#pragma unroll
    for (int im = 0; im < 4; im++)
#pragma unroll
        for (int jn = 0; jn < 4; jn++)
#pragma unroll
            for (int q = 0; q < 4; q++) acc[im][jn][q] = 0.0f;

    const int NK = DD / 16;   // 64

#pragma unroll
    for (int s = 0; s < 3; s++) {
#pragma unroll
        for (int h = 0; h < 2; h++) {
            int q = tid + h * 256;
            int tm_l = q >> 6, tk_l = (q >> 5) & 1, f4 = q & 31;
            size_t go = (size_t)tm_l * 16384 + (size_t)(2 * s + tk_l) * 128 + f4 * 4;
            cp16(As + s * STGF + q * 4, Abase + go);
            cp16(Bs + s * STGF + q * 4, Wbase + go);
        }
        asm volatile("cp.async.commit_group;\n");
    }

    for (int kt = 0; kt < NK; kt++) {
        if (kt < NK - 2)       asm volatile("cp.async.wait_group 2;\n");
        else if (kt == NK - 2) asm volatile("cp.async.wait_group 1;\n");
        else                   asm volatile("cp.async.wait_group 0;\n");
        __syncthreads();

        if (kt + 3 < NK) {
            const int nxt = (kt + 3) & 3;
#pragma unroll
            for (int h = 0; h < 2; h++) {
                int q = tid + h * 256;
                int tm_l = q >> 6, tk_l = (q >> 5) & 1, f4 = q & 31;
                size_t go = (size_t)tm_l * 16384 +
                            (size_t)(2 * (kt + 3) + tk_l) * 128 + f4 * 4;
                cp16(As + nxt * STGF + q * 4, Abase + go);
                cp16(Bs + nxt * STGF + q * 4, Wbase + go);
            }
            asm volatile("cp.async.commit_group;\n");
        }

        const float* Ac = As + (kt & 3) * STGF;
        const float* Bc = Bs + (kt & 3) * STGF;
#pragma unroll
        for (int tk_l = 0; tk_l < 2; tk_l++) {
            float4 af4[4], bf4[2];
#pragma unroll
            for (int im = 0; im < 4; im++)
                af4[im] = *(const float4*)(Ac + (((wm0 >> 4) + im) * 2 + tk_l) * 128 +
                                           lane * 4);
#pragma unroll
            for (int p = 0; p < 2; p++)
                bf4[p] = *(const float4*)(Bc + (((wn0 >> 4) + p) * 2 + tk_l) * 128 +
                                          lane * 4);
#pragma unroll
            for (int im = 0; im < 4; im++) {
                const unsigned* a = (const unsigned*)&af4[im];
#pragma unroll
                for (int jn = 0; jn < 4; jn++) {
                    const unsigned* bp = (const unsigned*)&bf4[jn >> 1];
                    unsigned b[2] = {bp[(jn & 1) * 2], bp[(jn & 1) * 2 + 1]};
                    mma_m16n8k8(acc[im][jn], a, b);
                }
            }
        }
    }

    // epilogue
#pragma unroll
    for (int im = 0; im < 4; im++) {
#pragma unroll
        for (int jn = 0; jn < 4; jn++) {
            int r = row0 + wm0 + im * 16 + g;
            int c = col0 + wn0 + jn * 8 + 2 * tig;
#pragma unroll
            for (int half = 0; half < 2; half++) {
                int rr = r + half * 8;
                float2 v = make_float2(acc[im][jn][half * 2 + 0],
                                       acc[im][jn][half * 2 + 1]);
                if (MODE == 1) {
                    int w = c >> 10;
                    int cl = c & 1023;
                    float* dst = (w == 0) ? C0 : (w == 1) ? C1 : C2;
                    int b = rr >> 11;
                    int s = rr & 2047;
                    int h = cl >> 6;
                    int d = cl & 63;
                    size_t off = (((size_t)(b * HH + h) * SS + s) * DK + d);
                    *(float2*)(dst + off) = v;
                } else {
                    *(float2*)(C0 + (size_t)rr * DD + c) = v;
                }
            }
        }
    }
}

// ---------------- Flash attention (causal) via tf32 mma ----------------
// BM=128, BN=64. 8 warps; warp w owns rows [16w,16w+16).
// Q fragments in registers; Q smem buffer reused for P. 2 CTAs/SM.
#define ALD 68

__global__ __launch_bounds__(256, 2) void attn_mma(const float* __restrict__ Q,
                                                   const float* __restrict__ K,
                                                   const float* __restrict__ V,
                                                   float* __restrict__ O) {
    extern __shared__ float sm[];
    float* Ps = sm;                    // [128][ALD]  (first holds Q, then P)
    float* Ks = Ps + 128 * ALD;        // [64][ALD]
    float* Vs = Ks + 64 * ALD;         // [64][ALD]

    const int tid = threadIdx.x;
    const int lane = tid & 31;
    const int wid = tid >> 5;
    const int g = lane >> 2;
    const int tig = lane & 3;
    const int qb = (gridDim.x - 1) - blockIdx.x;
    const int bh = blockIdx.y;
    const int q0 = qb * 128;
    const int row_base = wid * 16;

    const float* Qb = Q + (size_t)bh * SS * DK;
    const float* Kb = K + (size_t)bh * SS * DK;
    const float* Vb = V + (size_t)bh * SS * DK;

#pragma unroll
    for (int i = 0; i < 8; i++) {
        int idx = lane + 32 * i;
        int r = row_base + (idx >> 4);
        int c4 = (idx & 15) * 4;
        float4 v = *(const float4*)(Qb + (size_t)(q0 + r) * DK + c4);
        Ps[r * ALD + c4 + 0] = f2tf32f(v.x * 0.125f);
        Ps[r * ALD + c4 + 1] = f2tf32f(v.y * 0.125f);
        Ps[r * ALD + c4 + 2] = f2tf32f(v.z * 0.125f);
        Ps[r * ALD + c4 + 3] = f2tf32f(v.w * 0.125f);
    }
    __syncwarp();

    unsigned qf[8][4];
#pragma unroll
    for (int s = 0; s < 8; s++) {
        int k8 = s * 8;
        qf[s][0] = __float_as_uint(Ps[(row_base + g) * ALD + k8 + tig]);
        qf[s][1] = __float_as_uint(Ps[(row_base + g + 8) * ALD + k8 + tig]);
        qf[s][2] = __float_as_uint(Ps[(row_base + g) * ALD + k8 + tig + 4]);
        qf[s][3] = __float_as_uint(Ps[(row_base + g + 8) * ALD + k8 + tig + 4]);
    }
    __syncwarp();

    float m_i[2] = {NEG_BIG, NEG_BIG};
    float l_i[2] = {0.0f, 0.0f};
    float oacc[8][4];
#pragma unroll
    for (int jn = 0; jn < 8; jn++)
#pragma unroll
        for (int q = 0; q < 4; q++) oacc[jn][q] = 0.0f;

    const int nt = 2 * qb + 2;
    for (int t = 0; t < nt; t++) {
        const int kv0 = t * 64;
        __syncthreads();
        for (int idx = tid; idx < 64 * 16; idx += 256) {
            int r = idx >> 4, c4 = (idx & 15) * 4;
            float4 kv = *(const float4*)(Kb + (size_t)(kv0 + r) * DK + c4);
            float4 vv = *(const float4*)(Vb + (size_t)(kv0 + r) * DK + c4);
            Ks[r * ALD + c4 + 0] = f2tf32f(kv.x);
            Ks[r * ALD + c4 + 1] = f2tf32f(kv.y);
            Ks[r * ALD + c4 + 2] = f2tf32f(kv.z);
            Ks[r * ALD + c4 + 3] = f2tf32f(kv.w);
            Vs[r * ALD + c4 + 0] = f2tf32f(vv.x);
            Vs[r * ALD + c4 + 1] = f2tf32f(vv.y);
            Vs[r * ALD + c4 + 2] = f2tf32f(vv.z);
            Vs[r * ALD + c4 + 3] = f2tf32f(vv.w);
        }
        __syncthreads();

        float sacc[8][4];
#pragma unroll
        for (int jn = 0; jn < 8; jn++)
#pragma unroll
            for (int q = 0; q < 4; q++) sacc[jn][q] = 0.0f;

#pragma unroll
        for (int s = 0; s < 8; s++) {
            int k8 = s * 8;
#pragma unroll
            for (int jn = 0; jn < 8; jn++) {
                unsigned bf[2];
                bf[0] = __float_as_uint(Ks[(jn * 8 + g) * ALD + k8 + tig]);
                bf[1] = __float_as_uint(Ks[(jn * 8 + g) * ALD + k8 + tig + 4]);
                mma_m16n8k8(sacc[jn], qf[s], bf);
            }
        }

        if (t >= nt - 2) {
#pragma unroll
            for (int jn = 0; jn < 8; jn++)
#pragma unroll
                for (int q = 0; q < 4; q++) {
                    int row = q0 + row_base + g + (q >> 1) * 8;
                    int col = kv0 + jn * 8 + 2 * tig + (q & 1);
                    if (col > row) sacc[jn][q] = NEG_BIG;
                }
        }

#pragma unroll
        for (int h = 0; h < 2; h++) {
            float mx = NEG_BIG;
#pragma unroll
            for (int jn = 0; jn < 8; jn++)
                mx = fmaxf(mx, fmaxf(sacc[jn][2 * h], sacc[jn][2 * h + 1]));
            mx = fmaxf(mx, __shfl_xor_sync(0xffffffffu, mx, 1));
            mx = fmaxf(mx, __shfl_xor_sync(0xffffffffu, mx, 2));
            float mn = fmaxf(m_i[h], mx);
            float corr = __expf(m_i[h] - mn);
            m_i[h] = mn;
            float rs = 0.0f;
#pragma unroll
            for (int jn = 0; jn < 8; jn++) {
                float e0 = __expf(sacc[jn][2 * h] - mn);
                float e1 = __expf(sacc[jn][2 * h + 1] - mn);
                sacc[jn][2 * h] = e0;
                sacc[jn][2 * h + 1] = e1;
                rs += e0 + e1;
            }
            rs += __shfl_xor_sync(0xffffffffu, rs, 1);
            rs += __shfl_xor_sync(0xffffffffu, rs, 2);
            l_i[h] = l_i[h] * corr + rs;
#pragma unroll
            for (int jn = 0; jn < 8; jn++) {
                oacc[jn][2 * h] *= corr;
                oacc[jn][2 * h + 1] *= corr;
            }
        }

#pragma unroll
        for (int jn = 0; jn < 8; jn++) {
            float2 p0 = make_float2(f2tf32f(sacc[jn][0]), f2tf32f(sacc[jn][1]));
            float2 p1 = make_float2(f2tf32f(sacc[jn][2]), f2tf32f(sacc[jn][3]));
            *(float2*)(Ps + (row_base + g) * ALD + jn * 8 + 2 * tig) = p0;
            *(float2*)(Ps + (row_base + g + 8) * ALD + jn * 8 + 2 * tig) = p1;
        }
        __syncwarp();

#pragma unroll
        for (int s = 0; s < 8; s++) {
            int k8 = s * 8;
            unsigned af[4];
            af[0] = __float_as_uint(Ps[(row_base + g) * ALD + k8 + tig]);
            af[1] = __float_as_uint(Ps[(row_base + g + 8) * ALD + k8 + tig]);
            af[2] = __float_as_uint(Ps[(row_base + g) * ALD + k8 + tig + 4]);
            af[3] = __float_as_uint(Ps[(row_base + g + 8) * ALD + k8 + tig + 4]);
#pragma unroll
            for (int jn = 0; jn < 8; jn++) {
                unsigned bf[2];
                bf[0] = __float_as_uint(Vs[(k8 + tig) * ALD + jn * 8 + g]);
                bf[1] = __float_as_uint(Vs[(k8 + tig + 4) * ALD + jn * 8 + g]);
                mma_m16n8k8(oacc[jn], af, bf);
            }
        }
        __syncwarp();
    }

    // epilogue: write O into packed-A layout of g_attn (row = b*SS+s, col = h*64+d)
    const int b = bh >> 4, h = bh & 15;
#pragma unroll
    for (int hf = 0; hf < 2; hf++) {
        float inv = 1.0f / l_i[hf];
        int s = q0 + row_base + g + hf * 8;
        int r = b * SS + s;
#pragma unroll
        for (int jn = 0; jn < 8; jn++) {
            int c = h * DK + jn * 8 + 2 * tig;
            O[packA_addr(r, c)]     = f2tf32f(oacc[jn][2 * hf] * inv);
            O[packA_addr(r, c + 1)] = f2tf32f(oacc[jn][2 * hf + 1] * inv);
        }
    }
}

// ---------------- launch ----------------
extern "C" void kernel_launch(void* const* d_in, const int* in_sizes, int n_in,
                              void* d_out, int out_size) {
    const float* x  = (const float*)d_in[0];
    const float* wq = (const float*)d_in[1];
    const float* wk = (const float*)d_in[2];
    const float* wv = (const float*)d_in[3];
    const float* wo = (const float*)d_in[4];
    float* out = (float*)d_out;

    float *pq, *pk, *pv, *pa, *pxt, *pw4;
    cudaGetSymbolAddress((void**)&pq, g_q);
    cudaGetSymbolAddress((void**)&pk, g_k);
    cudaGetSymbolAddress((void**)&pv, g_v);
    cudaGetSymbolAddress((void**)&pa, g_attn);
    cudaGetSymbolAddress((void**)&pxt, g_xt);
    cudaGetSymbolAddress((void**)&pw4, g_w4);

    static const int attn_smem = (128 + 64 + 64) * ALD * sizeof(float);  // 69632
    static const int gemm_smem = 2 * GSTG * STGF * sizeof(float);        // 65536
    cudaFuncSetAttribute(attn_mma, cudaFuncAttributeMaxDynamicSharedMemorySize,
                         attn_smem);
    cudaFuncSetAttribute(gemm_pk<0>, cudaFuncAttributeMaxDynamicSharedMemorySize,
                         gemm_smem);
    cudaFuncSetAttribute(gemm_pk<1>, cudaFuncAttributeMaxDynamicSharedMemorySize,
                         gemm_smem);

    // pre-pass: pack X (A layout) and weights (B layout), tf32-rounded
    const int n4x = MM * DD / 4;
    const int n4w4 = 4 * DD * DD / 4;
    pack_a_kernel<<<(n4x + 255) / 256, 256>>>(x, pxt, n4x);
    pack_w4_kernel<<<(n4w4 + 255) / 256, 256>>>(wq, wk, wv, wo, pw4);

    // fused QKV projection: N = 3072
    dim3 gQKV(3 * DD / 128, MM / 128);   // (24, 64)
    gemm_pk<1><<<gQKV, 256, gemm_smem>>>(pxt, pw4, pq, pk, pv);

    dim3 gAttn(SS / 128, BB * HH);       // (16, 64)
    attn_mma<<<gAttn, 256, attn_smem>>>(pq, pk, pv, pa);

    // output projection
    dim3 gOut(DD / 128, MM / 128);       // (8, 64)
    gemm_pk<0><<<gOut, 256, gemm_smem>>>(pa, pw4 + 3 * DD * DD, out, nullptr, nullptr);
}

// round 10
// speedup vs baseline: 3.9274x; 1.0518x over previous
#include <cuda_runtime.h>
#include <cuda_bf16.h>
#include <math.h>

// Problem constants
#define BB 4
#define SS 2048
#define DD 1024
#define HH 16
#define DK 64
#define MM (BB * SS)          // 8192 rows
#define NEG_BIG (-1.0e30f)
// softmax scale with log2(e) folded in: 0.125 * 1.44269504
#define QSCALE 0.1803368801111137f

// ---------------- scratch (alloc-free: __device__ globals) ----------------
__device__ float g_q[BB * HH * SS * DK];     // [b,h,s,dk]  (pre-scaled, tf32)
__device__ float g_k[BB * HH * SS * DK];     // tf32-rounded
__device__ float g_v[BB * HH * SS * DK];     // tf32-rounded
__device__ float g_attn[MM * DD];            // packed-A layout (tf32)
__device__ float g_xt[MM * DD];              // packed-A layout (tf32)
__device__ float g_w4[4 * DD * DD];          // packed-B layout (tf32)

// ---------------- helpers ----------------
__device__ __forceinline__ unsigned f2tf32(float f) {
    unsigned r;
    asm("cvt.rna.tf32.f32 %0, %1;" : "=r"(r) : "f"(f));
    return r;
}
__device__ __forceinline__ float f2tf32f(float f) {
    return __uint_as_float(f2tf32(f));
}
__device__ __forceinline__ float ex2(float x) {
    float y;
    asm("ex2.approx.f32 %0, %1;" : "=f"(y) : "f"(x));
    return y;
}

__device__ __forceinline__ void mma_m16n8k8(float* d, const unsigned* a,
                                            const unsigned* b) {
    asm volatile(
        "mma.sync.aligned.m16n8k8.row.col.f32.tf32.tf32.f32 "
        "{%0,%1,%2,%3},{%4,%5,%6,%7},{%8,%9},{%0,%1,%2,%3};\n"
        : "+f"(d[0]), "+f"(d[1]), "+f"(d[2]), "+f"(d[3])
        : "r"(a[0]), "r"(a[1]), "r"(a[2]), "r"(a[3]), "r"(b[0]), "r"(b[1]));
}

__device__ __forceinline__ void cp16(void* smem, const void* gmem) {
    unsigned s = (unsigned)__cvta_generic_to_shared(smem);
    asm volatile("cp.async.cg.shared.global [%0], [%1], 16;\n" :: "r"(s), "l"(gmem));
}

// packed-A address: element (r, c) of an M x 1024 matrix
__device__ __forceinline__ size_t packA_addr(int r, int c) {
    return ((size_t)((r >> 4) * 128 + (c >> 3)) << 7) +
           ((r & 7) * 16 + (c & 3) * 4 + ((r >> 3) & 1) + 2 * ((c >> 2) & 1));
}

// ---------------- pre-pass: pack X (A layout) ----------------
__global__ void pack_a_kernel(const float* __restrict__ A, float* __restrict__ out,
                              int n4) {
    int i = blockIdx.x * blockDim.x + threadIdx.x;
    if (i >= n4) return;
    int tm = i >> 12;
    int tk = (i >> 5) & 127;
    int lane = i & 31;
    int g = lane >> 2, tig = lane & 3;
    int r0 = tm * 16, c0 = tk * 8;
    const float* p = A + (size_t)r0 * DD + c0;
    float4 v;
    v.x = f2tf32f(p[(size_t)g * DD + tig]);
    v.y = f2tf32f(p[(size_t)(g + 8) * DD + tig]);
    v.z = f2tf32f(p[(size_t)g * DD + tig + 4]);
    v.w = f2tf32f(p[(size_t)(g + 8) * DD + tig + 4]);
    ((float4*)out)[i] = v;
}

// ---------------- pre-pass: pack 4 weights (B layout) ----------------
__global__ void pack_w4_kernel(const float* __restrict__ w0,
                               const float* __restrict__ w1,
                               const float* __restrict__ w2,
                               const float* __restrict__ w3,
                               float* __restrict__ out) {
    const int per_w = DD * DD / 4;
    int j = blockIdx.x * blockDim.x + threadIdx.x;
    if (j >= 4 * per_w) return;
    int w = j / per_w, i = j - w * per_w;
    const float* W = (w == 0) ? w0 : (w == 1) ? w1 : (w == 2) ? w2 : w3;
    int tn = i >> 12;
    int tk = (i >> 5) & 127;
    int lane = i & 31;
    int g = lane >> 2, tig = lane & 3;
    int n0 = tn * 16, k0 = tk * 8;
    const float* p = W + (size_t)n0 * DD + k0;
    float4 v;
    v.x = f2tf32f(p[(size_t)g * DD + tig]);
    v.y = f2tf32f(p[(size_t)g * DD + tig + 4]);
    v.z = f2tf32f(p[(size_t)(g + 8) * DD + tig]);
    v.w = f2tf32f(p[(size_t)(g + 8) * DD + tig + 4]);
    ((float4*)(out + (size_t)w * DD * DD))[j - w * per_w] = v;
}

// ---------------- GEMM core: packed A x packed B -> C ----------------
// MODE 0: C row-major [M,1024] (out projection, raw fp32)
// MODE 1: QKV scatter into [b,h,s,dk]; Q pre-scaled by QSCALE, all tf32-rounded.
#define GSTG 4
#define STGF 2048

template <int MODE>
__global__ __launch_bounds__(256, 2) void gemm_pk(const float* __restrict__ A,
                                                  const float* __restrict__ W,
                                                  float* __restrict__ C0,
                                                  float* __restrict__ C1,
                                                  float* __restrict__ C2) {
    extern __shared__ float gsm[];
    float* As = gsm;
    float* Bs = gsm + GSTG * STGF;

    const int tid = threadIdx.x;
    const int lane = tid & 31;
    const int wid = tid >> 5;
    const int g = lane >> 2;
    const int tig = lane & 3;
    const int wm0 = (wid >> 2) * 64;
    const int wn0 = (wid & 3) * 32;
    const int row0 = blockIdx.y * 128;
    const int col0 = blockIdx.x * 128;

    const float* Abase = A + (size_t)(row0 >> 4) * 16384;
    const float* Wbase = W + (size_t)(col0 >> 4) * 16384;

    float acc[4][4][4];
#pragma unroll
    for (int im = 0; im < 4; im++)
#pragma unroll
        for (int jn = 0; jn < 4; jn++)
#pragma unroll
            for (int q = 0; q < 4; q++) acc[im][jn][q] = 0.0f;

    const int NK = DD / 16;

#pragma unroll
    for (int s = 0; s < 3; s++) {
#pragma unroll
        for (int h = 0; h < 2; h++) {
            int q = tid + h * 256;
            int tm_l = q >> 6, tk_l = (q >> 5) & 1, f4 = q & 31;
            size_t go = (size_t)tm_l * 16384 + (size_t)(2 * s + tk_l) * 128 + f4 * 4;
            cp16(As + s * STGF + q * 4, Abase + go);
            cp16(Bs + s * STGF + q * 4, Wbase + go);
        }
        asm volatile("cp.async.commit_group;\n");
    }

    for (int kt = 0; kt < NK; kt++) {
        if (kt < NK - 2)       asm volatile("cp.async.wait_group 2;\n");
        else if (kt == NK - 2) asm volatile("cp.async.wait_group 1;\n");
        else                   asm volatile("cp.async.wait_group 0;\n");
        __syncthreads();

        if (kt + 3 < NK) {
            const int nxt = (kt + 3) & 3;
#pragma unroll
            for (int h = 0; h < 2; h++) {
                int q = tid + h * 256;
                int tm_l = q >> 6, tk_l = (q >> 5) & 1, f4 = q & 31;
                size_t go = (size_t)tm_l * 16384 +
                            (size_t)(2 * (kt + 3) + tk_l) * 128 + f4 * 4;
                cp16(As + nxt * STGF + q * 4, Abase + go);
                cp16(Bs + nxt * STGF + q * 4, Wbase + go);
            }
            asm volatile("cp.async.commit_group;\n");
        }

        const float* Ac = As + (kt & 3) * STGF;
        const float* Bc = Bs + (kt & 3) * STGF;
#pragma unroll
        for (int tk_l = 0; tk_l < 2; tk_l++) {
            float4 af4[4], bf4[2];
#pragma unroll
            for (int im = 0; im < 4; im++)
                af4[im] = *(const float4*)(Ac + (((wm0 >> 4) + im) * 2 + tk_l) * 128 +
                                           lane * 4);
#pragma unroll
            for (int p = 0; p < 2; p++)
                bf4[p] = *(const float4*)(Bc + (((wn0 >> 4) + p) * 2 + tk_l) * 128 +
                                          lane * 4);
#pragma unroll
            for (int im = 0; im < 4; im++) {
                const unsigned* a = (const unsigned*)&af4[im];
#pragma unroll
                for (int jn = 0; jn < 4; jn++) {
                    const unsigned* bp = (const unsigned*)&bf4[jn >> 1];
                    unsigned b[2] = {bp[(jn & 1) * 2], bp[(jn & 1) * 2 + 1]};
                    mma_m16n8k8(acc[im][jn], a, b);
                }
            }
        }
    }

#pragma unroll
    for (int im = 0; im < 4; im++) {
#pragma unroll
        for (int jn = 0; jn < 4; jn++) {
            int r = row0 + wm0 + im * 16 + g;
            int c = col0 + wn0 + jn * 8 + 2 * tig;
#pragma unroll
            for (int half = 0; half < 2; half++) {
                int rr = r + half * 8;
                float2 v = make_float2(acc[im][jn][half * 2 + 0],
                                       acc[im][jn][half * 2 + 1]);
                if (MODE == 1) {
                    int w = c >> 10;
                    int cl = c & 1023;
                    // Q: fold softmax scale (incl log2e); K/V: tf32-round.
                    float sc = (w == 0) ? QSCALE : 1.0f;
                    v.x = f2tf32f(v.x * sc);
                    v.y = f2tf32f(v.y * sc);
                    float* dst = (w == 0) ? C0 : (w == 1) ? C1 : C2;
                    int b = rr >> 11;
                    int s = rr & 2047;
                    int h = cl >> 6;
                    int d = cl & 63;
                    size_t off = (((size_t)(b * HH + h) * SS + s) * DK + d);
                    *(float2*)(dst + off) = v;
                } else {
                    *(float2*)(C0 + (size_t)rr * DD + c) = v;
                }
            }
        }
    }
}

// ---------------- Flash attention (causal), tf32 mma + cp.async K/V --------
// BM=128, BN=64. 8 warps; warp w owns rows [16w,16w+16).
// Q fragments loaded from gmem into registers (inputs already scaled+tf32).
// K/V double-buffered via cp.async into padded smem (row stride ALD=68).
// smem = (128 + 2*128) * 68 * 4 = 104448 B.
#define ALD 68

__global__ __launch_bounds__(256, 2) void attn_mma(const float* __restrict__ Q,
                                                   const float* __restrict__ K,
                                                   const float* __restrict__ V,
                                                   float* __restrict__ O) {
    extern __shared__ float sm[];
    float* Ps = sm;                     // [128][ALD]
    float* KVs = sm + 128 * ALD;        // 2 stages x (K[64][ALD], V[64][ALD])

    const int tid = threadIdx.x;
    const int lane = tid & 31;
    const int wid = tid >> 5;
    const int g = lane >> 2;
    const int tig = lane & 3;
    const int qb = (gridDim.x - 1) - blockIdx.x;
    const int bh = blockIdx.y;
    const int q0 = qb * 128;
    const int row_base = wid * 16;

    const float* Qb = Q + (size_t)bh * SS * DK;
    const float* Kb = K + (size_t)bh * SS * DK;
    const float* Vb = V + (size_t)bh * SS * DK;

    // Q fragments straight from gmem (already scaled + tf32)
    unsigned qf[8][4];
    {
        const float* qr0 = Qb + (size_t)(q0 + row_base + g) * DK;
        const float* qr1 = Qb + (size_t)(q0 + row_base + g + 8) * DK;
#pragma unroll
        for (int s = 0; s < 8; s++) {
            int k8 = s * 8;
            qf[s][0] = __float_as_uint(qr0[k8 + tig]);
            qf[s][1] = __float_as_uint(qr1[k8 + tig]);
            qf[s][2] = __float_as_uint(qr0[k8 + tig + 4]);
            qf[s][3] = __float_as_uint(qr1[k8 + tig + 4]);
        }
    }

    float m_i[2] = {NEG_BIG, NEG_BIG};
    float l_i[2] = {0.0f, 0.0f};
    float oacc[8][4];
#pragma unroll
    for (int jn = 0; jn < 8; jn++)
#pragma unroll
        for (int q = 0; q < 4; q++) oacc[jn][q] = 0.0f;

    const int nt = 2 * qb + 2;

    // stage fill: K then V, 4 chunks each per thread
    auto fill = [&](int st, int kv0) {
        float* Kd = KVs + st * (128 * ALD);
        float* Vd = Kd + 64 * ALD;
#pragma unroll
        for (int i = 0; i < 4; i++) {
            int c = tid + 256 * i;          // 0..1023
            int r = c >> 4, c4 = c & 15;
            cp16(Kd + r * ALD + c4 * 4, Kb + (size_t)(kv0 + r) * DK + c4 * 4);
        }
#pragma unroll
        for (int i = 0; i < 4; i++) {
            int c = tid + 256 * i;
            int r = c >> 4, c4 = c & 15;
            cp16(Vd + r * ALD + c4 * 4, Vb + (size_t)(kv0 + r) * DK + c4 * 4);
        }
        asm volatile("cp.async.commit_group;\n");
    };

    fill(0, 0);

    for (int t = 0; t < nt; t++) {
        asm volatile("cp.async.wait_group 0;\n");
        __syncthreads();   // stage cur visible to all; prev compute on stage nxt done

        const int cur = t & 1;
        if (t + 1 < nt) fill(cur ^ 1, (t + 1) * 64);

        const float* Ks = KVs + cur * (128 * ALD);
        const float* Vs = Ks + 64 * ALD;

        // ---- S = Q K^T ----
        float sacc[8][4];
#pragma unroll
        for (int jn = 0; jn < 8; jn++)
#pragma unroll
            for (int q = 0; q < 4; q++) sacc[jn][q] = 0.0f;

#pragma unroll
        for (int s = 0; s < 8; s++) {
            int k8 = s * 8;
#pragma unroll
            for (int jn = 0; jn < 8; jn++) {
                unsigned bf[2];
                bf[0] = __float_as_uint(Ks[(jn * 8 + g) * ALD + k8 + tig]);
                bf[1] = __float_as_uint(Ks[(jn * 8 + g) * ALD + k8 + tig + 4]);
                mma_m16n8k8(sacc[jn], qf[s], bf);
            }
        }

        if (t >= nt - 2) {
            const int kv0 = t * 64;
#pragma unroll
            for (int jn = 0; jn < 8; jn++)
#pragma unroll
                for (int q = 0; q < 4; q++) {
                    int row = q0 + row_base + g + (q >> 1) * 8;
                    int col = kv0 + jn * 8 + 2 * tig + (q & 1);
                    if (col > row) sacc[jn][q] = NEG_BIG;
                }
        }

        // ---- online softmax (base-2) ----
#pragma unroll
        for (int h = 0; h < 2; h++) {
            float mx = NEG_BIG;
#pragma unroll
            for (int jn = 0; jn < 8; jn++)
                mx = fmaxf(mx, fmaxf(sacc[jn][2 * h], sacc[jn][2 * h + 1]));
            mx = fmaxf(mx, __shfl_xor_sync(0xffffffffu, mx, 1));
            mx = fmaxf(mx, __shfl_xor_sync(0xffffffffu, mx, 2));
            float mn = fmaxf(m_i[h], mx);
            float corr = ex2(m_i[h] - mn);
            m_i[h] = mn;
            float rs = 0.0f;
#pragma unroll
            for (int jn = 0; jn < 8; jn++) {
                float e0 = ex2(sacc[jn][2 * h] - mn);
                float e1 = ex2(sacc[jn][2 * h + 1] - mn);
                sacc[jn][2 * h] = e0;
                sacc[jn][2 * h + 1] = e1;
                rs += e0 + e1;
            }
            rs += __shfl_xor_sync(0xffffffffu, rs, 1);
            rs += __shfl_xor_sync(0xffffffffu, rs, 2);
            l_i[h] = l_i[h] * corr + rs;
#pragma unroll
            for (int jn = 0; jn < 8; jn++) {
                oacc[jn][2 * h] *= corr;
                oacc[jn][2 * h + 1] *= corr;
            }
        }

        // ---- P -> smem (warp-local rows) ----
#pragma unroll
        for (int jn = 0; jn < 8; jn++) {
            float2 p0 = make_float2(f2tf32f(sacc[jn][0]), f2tf32f(sacc[jn][1]));
            float2 p1 = make_float2(f2tf32f(sacc[jn][2]), f2tf32f(sacc[jn][3]));
            *(float2*)(Ps + (row_base + g) * ALD + jn * 8 + 2 * tig) = p0;
            *(float2*)(Ps + (row_base + g + 8) * ALD + jn * 8 + 2 * tig) = p1;
        }
        __syncwarp();

        // ---- O += P V ----
#pragma unroll
        for (int s = 0; s < 8; s++) {
            int k8 = s * 8;
            unsigned af[4];
            af[0] = __float_as_uint(Ps[(row_base + g) * ALD + k8 + tig]);
            af[1] = __float_as_uint(Ps[(row_base + g + 8) * ALD + k8 + tig]);
            af[2] = __float_as_uint(Ps[(row_base + g) * ALD + k8 + tig + 4]);
            af[3] = __float_as_uint(Ps[(row_base + g + 8) * ALD + k8 + tig + 4]);
#pragma unroll
            for (int jn = 0; jn < 8; jn++) {
                unsigned bf[2];
                bf[0] = __float_as_uint(Vs[(k8 + tig) * ALD + jn * 8 + g]);
                bf[1] = __float_as_uint(Vs[(k8 + tig + 4) * ALD + jn * 8 + g]);
                mma_m16n8k8(oacc[jn], af, bf);
            }
        }
        __syncwarp();
    }

    // epilogue: packed-A write of O (row = b*SS+s, col = h*64+d)
    const int b = bh >> 4, h = bh & 15;
#pragma unroll
    for (int hf = 0; hf < 2; hf++) {
        float inv = 1.0f / l_i[hf];
        int s = q0 + row_base + g + hf * 8;
        int r = b * SS + s;
#pragma unroll
        for (int jn = 0; jn < 8; jn++) {
            int c = h * DK + jn * 8 + 2 * tig;
            O[packA_addr(r, c)]     = f2tf32f(oacc[jn][2 * hf] * inv);
            O[packA_addr(r, c + 1)] = f2tf32f(oacc[jn][2 * hf + 1] * inv);
        }
    }
}

// ---------------- launch ----------------
extern "C" void kernel_launch(void* const* d_in, const int* in_sizes, int n_in,
                              void* d_out, int out_size) {
    const float* x  = (const float*)d_in[0];
    const float* wq = (const float*)d_in[1];
    const float* wk = (const float*)d_in[2];
    const float* wv = (const float*)d_in[3];
    const float* wo = (const float*)d_in[4];
    float* out = (float*)d_out;

    float *pq, *pk, *pv, *pa, *pxt, *pw4;
    cudaGetSymbolAddress((void**)&pq, g_q);
    cudaGetSymbolAddress((void**)&pk, g_k);
    cudaGetSymbolAddress((void**)&pv, g_v);
    cudaGetSymbolAddress((void**)&pa, g_attn);
    cudaGetSymbolAddress((void**)&pxt, g_xt);
    cudaGetSymbolAddress((void**)&pw4, g_w4);

    static const int attn_smem = (128 + 256) * ALD * sizeof(float);   // 104448
    static const int gemm_smem = 2 * GSTG * STGF * sizeof(float);     // 65536
    cudaFuncSetAttribute(attn_mma, cudaFuncAttributeMaxDynamicSharedMemorySize,
                         attn_smem);
    cudaFuncSetAttribute(gemm_pk<0>, cudaFuncAttributeMaxDynamicSharedMemorySize,
                         gemm_smem);
    cudaFuncSetAttribute(gemm_pk<1>, cudaFuncAttributeMaxDynamicSharedMemorySize,
                         gemm_smem);

    const int n4x = MM * DD / 4;
    const int n4w4 = 4 * DD * DD / 4;
    pack_a_kernel<<<(n4x + 255) / 256, 256>>>(x, pxt, n4x);
    pack_w4_kernel<<<(n4w4 + 255) / 256, 256>>>(wq, wk, wv, wo, pw4);

    dim3 gQKV(3 * DD / 128, MM / 128);   // (24, 64)
    gemm_pk<1><<<gQKV, 256, gemm_smem>>>(pxt, pw4, pq, pk, pv);

    dim3 gAttn(SS / 128, BB * HH);       // (16, 64)
    attn_mma<<<gAttn, 256, attn_smem>>>(pq, pk, pv, pa);

    dim3 gOut(DD / 128, MM / 128);       // (8, 64)
    gemm_pk<0><<<gOut, 256, gemm_smem>>>(pa, pw4 + 3 * DD * DD, out, nullptr, nullptr);
}

// round 12
// speedup vs baseline: 4.6582x; 1.1861x over previous
#include <cuda_runtime.h>
#include <cuda_bf16.h>
#include <math.h>

// Problem constants
#define BB 4
#define SS 2048
#define DD 1024
#define HH 16
#define DK 64
#define MM (BB * SS)          // 8192 rows
#define NEG_BIG (-1.0e30f)
// softmax scale with log2(e) folded in: 0.125 * 1.44269504
#define QSCALE 0.1803368801111137f
#define KVSZ 131072           // floats per (b,h) packed K or V (2048*64)

// ---------------- scratch (alloc-free: __device__ globals) ----------------
__device__ float g_q[BB * HH * SS * DK];     // [b,h,s,dk]  (pre-scaled, tf32)
__device__ float g_k[BB * HH * SS * DK];     // packed-B per (b,h): n=s, k=d
__device__ float g_v[BB * HH * SS * DK];     // packed-B per (b,h): n=d, k=s
__device__ float g_attn[MM * DD];            // packed-A layout (tf32)
__device__ float g_xt[MM * DD];              // packed-A layout (tf32)
__device__ float g_w4[4 * DD * DD];          // packed-B layout (tf32)

// ---------------- helpers ----------------
__device__ __forceinline__ unsigned f2tf32(float f) {
    unsigned r;
    asm("cvt.rna.tf32.f32 %0, %1;" : "=r"(r) : "f"(f));
    return r;
}
__device__ __forceinline__ float f2tf32f(float f) {
    return __uint_as_float(f2tf32(f));
}
__device__ __forceinline__ float ex2(float x) {
    float y;
    asm("ex2.approx.f32 %0, %1;" : "=f"(y) : "f"(x));
    return y;
}

__device__ __forceinline__ void mma_m16n8k8(float* d, const unsigned* a,
                                            const unsigned* b) {
    asm volatile(
        "mma.sync.aligned.m16n8k8.row.col.f32.tf32.tf32.f32 "
        "{%0,%1,%2,%3},{%4,%5,%6,%7},{%8,%9},{%0,%1,%2,%3};\n"
        : "+f"(d[0]), "+f"(d[1]), "+f"(d[2]), "+f"(d[3])
        : "r"(a[0]), "r"(a[1]), "r"(a[2]), "r"(a[3]), "r"(b[0]), "r"(b[1]));
}

__device__ __forceinline__ void cp16(void* smem, const void* gmem) {
    unsigned s = (unsigned)__cvta_generic_to_shared(smem);
    asm volatile("cp.async.cg.shared.global [%0], [%1], 16;\n" :: "r"(s), "l"(gmem));
}

// packed-A address: element (r, c); k-tiles per row = 128 (K=1024)
__device__ __forceinline__ size_t packA_addr(int r, int c) {
    return ((size_t)((r >> 4) * 128 + (c >> 3)) << 7) +
           ((r & 7) * 16 + (c & 3) * 4 + ((r >> 3) & 1) + 2 * ((c >> 2) & 1));
}
// packed-B element address within one (b,h) K buffer: n=s (2048), k=d (64)
__device__ __forceinline__ size_t packK_addr(int s, int d) {
    return ((size_t)((s >> 4) * 8 + (d >> 3)) << 7) +
           ((s & 7) * 16 + (d & 3) * 4 + ((d >> 2) & 1) + 2 * ((s >> 3) & 1));
}
// packed-B element address within one (b,h) V buffer: n=d (64), k=s (2048),
// tk-major tiling so a 64-kv slab is contiguous
__device__ __forceinline__ size_t packV_addr(int d, int s) {
    return ((size_t)((s >> 3) * 4 + (d >> 4)) << 7) +
           ((d & 7) * 16 + (s & 3) * 4 + ((s >> 2) & 1) + 2 * ((d >> 3) & 1));
}

// ---------------- pre-pass: pack X (A layout) ----------------
__global__ void pack_a_kernel(const float* __restrict__ A, float* __restrict__ out,
                              int n4) {
    int i = blockIdx.x * blockDim.x + threadIdx.x;
    if (i >= n4) return;
    int tm = i >> 12;
    int tk = (i >> 5) & 127;
    int lane = i & 31;
    int g = lane >> 2, tig = lane & 3;
    int r0 = tm * 16, c0 = tk * 8;
    const float* p = A + (size_t)r0 * DD + c0;
    float4 v;
    v.x = f2tf32f(p[(size_t)g * DD + tig]);
    v.y = f2tf32f(p[(size_t)(g + 8) * DD + tig]);
    v.z = f2tf32f(p[(size_t)g * DD + tig + 4]);
    v.w = f2tf32f(p[(size_t)(g + 8) * DD + tig + 4]);
    ((float4*)out)[i] = v;
}

// ---------------- pre-pass: pack 4 weights (B layout) ----------------
__global__ void pack_w4_kernel(const float* __restrict__ w0,
                               const float* __restrict__ w1,
                               const float* __restrict__ w2,
                               const float* __restrict__ w3,
                               float* __restrict__ out) {
    const int per_w = DD * DD / 4;
    int j = blockIdx.x * blockDim.x + threadIdx.x;
    if (j >= 4 * per_w) return;
    int w = j / per_w, i = j - w * per_w;
    const float* W = (w == 0) ? w0 : (w == 1) ? w1 : (w == 2) ? w2 : w3;
    int tn = i >> 12;
    int tk = (i >> 5) & 127;
    int lane = i & 31;
    int g = lane >> 2, tig = lane & 3;
    int n0 = tn * 16, k0 = tk * 8;
    const float* p = W + (size_t)n0 * DD + k0;
    float4 v;
    v.x = f2tf32f(p[(size_t)g * DD + tig]);
    v.y = f2tf32f(p[(size_t)g * DD + tig + 4]);
    v.z = f2tf32f(p[(size_t)(g + 8) * DD + tig]);
    v.w = f2tf32f(p[(size_t)(g + 8) * DD + tig + 4]);
    ((float4*)(out + (size_t)w * DD * DD))[j - w * per_w] = v;
}

// ---------------- GEMM core: packed A x packed B -> C ----------------
// MODE 0: C row-major [M,1024] (out projection, raw fp32)
// MODE 1: QKV. Q -> [b,h,s,dk] scaled+tf32; K/V -> packed-B per (b,h), tf32.
#define GSTG 4
#define STGF 2048

template <int MODE>
__global__ __launch_bounds__(256, 2) void gemm_pk(const float* __restrict__ A,
                                                  const float* __restrict__ W,
                                                  float* __restrict__ C0,
                                                  float* __restrict__ C1,
                                                  float* __restrict__ C2) {
    extern __shared__ float gsm[];
    float* As = gsm;
    float* Bs = gsm + GSTG * STGF;

    const int tid = threadIdx.x;
    const int lane = tid & 31;
    const int wid = tid >> 5;
    const int g = lane >> 2;
    const int tig = lane & 3;
    const int wm0 = (wid >> 2) * 64;
    const int wn0 = (wid & 3) * 32;
    const int row0 = blockIdx.y * 128;
    const int col0 = blockIdx.x * 128;

    const float* Abase = A + (size_t)(row0 >> 4) * 16384;
    const float* Wbase = W + (size_t)(col0 >> 4) * 16384;

    float acc[4][4][4];
#pragma unroll
    for (int im = 0; im < 4; im++)
#pragma unroll
        for (int jn = 0; jn < 4; jn++)
#pragma unroll
            for (int q = 0; q < 4; q++) acc[im][jn][q] = 0.0f;

    const int NK = DD / 16;

#pragma unroll
    for (int s = 0; s < 3; s++) {
#pragma unroll
        for (int h = 0; h < 2; h++) {
            int q = tid + h * 256;
            int tm_l = q >> 6, tk_l = (q >> 5) & 1, f4 = q & 31;
            size_t go = (size_t)tm_l * 16384 + (size_t)(2 * s + tk_l) * 128 + f4 * 4;
            cp16(As + s * STGF + q * 4, Abase + go);
            cp16(Bs + s * STGF + q * 4, Wbase + go);
        }
        asm volatile("cp.async.commit_group;\n");
    }

    for (int kt = 0; kt < NK; kt++) {
        if (kt < NK - 2)       asm volatile("cp.async.wait_group 2;\n");
        else if (kt == NK - 2) asm volatile("cp.async.wait_group 1;\n");
        else                   asm volatile("cp.async.wait_group 0;\n");
        __syncthreads();

        if (kt + 3 < NK) {
            const int nxt = (kt + 3) & 3;
#pragma unroll
            for (int h = 0; h < 2; h++) {
                int q = tid + h * 256;
                int tm_l = q >> 6, tk_l = (q >> 5) & 1, f4 = q & 31;
                size_t go = (size_t)tm_l * 16384 +
                            (size_t)(2 * (kt + 3) + tk_l) * 128 + f4 * 4;
                cp16(As + nxt * STGF + q * 4, Abase + go);
                cp16(Bs + nxt * STGF + q * 4, Wbase + go);
            }
            asm volatile("cp.async.commit_group;\n");
        }

        const float* Ac = As + (kt & 3) * STGF;
        const float* Bc = Bs + (kt & 3) * STGF;
#pragma unroll
        for (int tk_l = 0; tk_l < 2; tk_l++) {
            float4 af4[4], bf4[2];
#pragma unroll
            for (int im = 0; im < 4; im++)
                af4[im] = *(const float4*)(Ac + (((wm0 >> 4) + im) * 2 + tk_l) * 128 +
                                           lane * 4);
#pragma unroll
            for (int p = 0; p < 2; p++)
                bf4[p] = *(const float4*)(Bc + (((wn0 >> 4) + p) * 2 + tk_l) * 128 +
                                          lane * 4);
#pragma unroll
            for (int im = 0; im < 4; im++) {
                const unsigned* a = (const unsigned*)&af4[im];
#pragma unroll
                for (int jn = 0; jn < 4; jn++) {
                    const unsigned* bp = (const unsigned*)&bf4[jn >> 1];
                    unsigned b[2] = {bp[(jn & 1) * 2], bp[(jn & 1) * 2 + 1]};
                    mma_m16n8k8(acc[im][jn], a, b);
                }
            }
        }
    }

#pragma unroll
    for (int im = 0; im < 4; im++) {
#pragma unroll
        for (int jn = 0; jn < 4; jn++) {
            int r = row0 + wm0 + im * 16 + g;
            int c = col0 + wn0 + jn * 8 + 2 * tig;
#pragma unroll
            for (int half = 0; half < 2; half++) {
                int rr = r + half * 8;
                float2 v = make_float2(acc[im][jn][half * 2 + 0],
                                       acc[im][jn][half * 2 + 1]);
                if (MODE == 1) {
                    int w = c >> 10;
                    int cl = c & 1023;
                    int b = rr >> 11;
                    int s = rr & 2047;
                    int h = cl >> 6;
                    int d = cl & 63;
                    if (w == 0) {
                        v.x = f2tf32f(v.x * QSCALE);
                        v.y = f2tf32f(v.y * QSCALE);
                        size_t off = (((size_t)(b * HH + h) * SS + s) * DK + d);
                        *(float2*)(C0 + off) = v;
                    } else if (w == 1) {
                        float* dst = C1 + (size_t)(b * HH + h) * KVSZ;
                        dst[packK_addr(s, d)]     = f2tf32f(v.x);
                        dst[packK_addr(s, d + 1)] = f2tf32f(v.y);
                    } else {
                        float* dst = C2 + (size_t)(b * HH + h) * KVSZ;
                        dst[packV_addr(d, s)]     = f2tf32f(v.x);
                        dst[packV_addr(d + 1, s)] = f2tf32f(v.y);
                    }
                } else {
                    *(float2*)(C0 + (size_t)rr * DD + c) = v;
                }
            }
        }
    }
}

// ---------------- Flash attention (causal), packed K/V fragments ----------
// BM=128, BN=64. 8 warps; warp w owns rows [16w,16w+16).
// K/V arrive in packed-B tile layout -> mainloop frag loads are LDS.128.
// smem: Ps[128*68] + 2 stages x (K 4096 + V 4096) = 100352 B.
#define ALD 68

__global__ __launch_bounds__(256, 2) void attn_mma(const float* __restrict__ Q,
                                                   const float* __restrict__ K,
                                                   const float* __restrict__ V,
                                                   float* __restrict__ O) {
    extern __shared__ float sm[];
    float* Ps = sm;                     // [128][ALD]
    float* KVs = sm + 128 * ALD;        // 2 x [K:4096 | V:4096]

    const int tid = threadIdx.x;
    const int lane = tid & 31;
    const int wid = tid >> 5;
    const int g = lane >> 2;
    const int tig = lane & 3;
    const int qb = (gridDim.x - 1) - blockIdx.x;
    const int bh = blockIdx.y;
    const int q0 = qb * 128;
    const int row_base = wid * 16;

    const float* Qb = Q + (size_t)bh * SS * DK;
    const float* Kb = K + (size_t)bh * KVSZ;
    const float* Vb = V + (size_t)bh * KVSZ;

    // Q fragments straight from gmem (already scaled + tf32)
    unsigned qf[8][4];
    {
        const float* qr0 = Qb + (size_t)(q0 + row_base + g) * DK;
        const float* qr1 = Qb + (size_t)(q0 + row_base + g + 8) * DK;
#pragma unroll
        for (int s = 0; s < 8; s++) {
            int k8 = s * 8;
            qf[s][0] = __float_as_uint(qr0[k8 + tig]);
            qf[s][1] = __float_as_uint(qr1[k8 + tig]);
            qf[s][2] = __float_as_uint(qr0[k8 + tig + 4]);
            qf[s][3] = __float_as_uint(qr1[k8 + tig + 4]);
        }
    }

    float m_i[2] = {NEG_BIG, NEG_BIG};
    float l_i[2] = {0.0f, 0.0f};
    float oacc[8][4];
#pragma unroll
    for (int jn = 0; jn < 8; jn++)
#pragma unroll
        for (int q = 0; q < 4; q++) oacc[jn][q] = 0.0f;

    const int nt = 2 * qb + 2;

    // stage fill: K slab (contiguous 4096) + V slab (contiguous 4096)
    auto fill = [&](int st, int kv0) {
        float* Kd = KVs + st * 8192;
        const float* ks = Kb + (size_t)(kv0 >> 4) * 1024;
        const float* vs = Vb + (size_t)(kv0 >> 3) * 512;
#pragma unroll
        for (int i = 0; i < 4; i++) {
            int idx = tid + 256 * i;        // 0..1023
            cp16(Kd + idx * 4, ks + idx * 4);
        }
#pragma unroll
        for (int i = 0; i < 4; i++) {
            int idx = tid + 256 * i;
            cp16(Kd + 4096 + idx * 4, vs + idx * 4);
        }
        asm volatile("cp.async.commit_group;\n");
    };

    fill(0, 0);

    for (int t = 0; t < nt; t++) {
        asm volatile("cp.async.wait_group 0;\n");
        __syncthreads();

        const int cur = t & 1;
        if (t + 1 < nt) fill(cur ^ 1, (t + 1) * 64);

        const float* Ks = KVs + cur * 8192;
        const float* Vs = Ks + 4096;

        // ---- S = Q K^T : packed K frags, LDS.128 ----
        float sacc[8][4];
#pragma unroll
        for (int jn = 0; jn < 8; jn++)
#pragma unroll
            for (int q = 0; q < 4; q++) sacc[jn][q] = 0.0f;

#pragma unroll
        for (int s = 0; s < 8; s++) {
#pragma unroll
            for (int j16 = 0; j16 < 4; j16++) {
                float4 b4 = *(const float4*)(Ks + (j16 * 8 + s) * 128 + lane * 4);
                const unsigned* bp = (const unsigned*)&b4;
                mma_m16n8k8(sacc[j16 * 2], qf[s], bp);
                mma_m16n8k8(sacc[j16 * 2 + 1], qf[s], bp + 2);
            }
        }

        if (t >= nt - 2) {
            const int kv0 = t * 64;
#pragma unroll
            for (int jn = 0; jn < 8; jn++)
#pragma unroll
                for (int q = 0; q < 4; q++) {
                    int row = q0 + row_base + g + (q >> 1) * 8;
                    int col = kv0 + jn * 8 + 2 * tig + (q & 1);
                    if (col > row) sacc[jn][q] = NEG_BIG;
                }
        }

        // ---- online softmax (base-2) ----
#pragma unroll
        for (int h = 0; h < 2; h++) {
            float mx = NEG_BIG;
#pragma unroll
            for (int jn = 0; jn < 8; jn++)
                mx = fmaxf(mx, fmaxf(sacc[jn][2 * h], sacc[jn][2 * h + 1]));
            mx = fmaxf(mx, __shfl_xor_sync(0xffffffffu, mx, 1));
            mx = fmaxf(mx, __shfl_xor_sync(0xffffffffu, mx, 2));
            float mn = fmaxf(m_i[h], mx);
            float corr = ex2(m_i[h] - mn);
            m_i[h] = mn;
            float rs = 0.0f;
#pragma unroll
            for (int jn = 0; jn < 8; jn++) {
                float e0 = ex2(sacc[jn][2 * h] - mn);
                float e1 = ex2(sacc[jn][2 * h + 1] - mn);
                sacc[jn][2 * h] = e0;
                sacc[jn][2 * h + 1] = e1;
                rs += e0 + e1;
            }
            rs += __shfl_xor_sync(0xffffffffu, rs, 1);
            rs += __shfl_xor_sync(0xffffffffu, rs, 2);
            l_i[h] = l_i[h] * corr + rs;
#pragma unroll
            for (int jn = 0; jn < 8; jn++) {
                oacc[jn][2 * h] *= corr;
                oacc[jn][2 * h + 1] *= corr;
            }
        }

        // ---- P -> smem (warp-local rows) ----
#pragma unroll
        for (int jn = 0; jn < 8; jn++) {
            float2 p0 = make_float2(f2tf32f(sacc[jn][0]), f2tf32f(sacc[jn][1]));
            float2 p1 = make_float2(f2tf32f(sacc[jn][2]), f2tf32f(sacc[jn][3]));
            *(float2*)(Ps + (row_base + g) * ALD + jn * 8 + 2 * tig) = p0;
            *(float2*)(Ps + (row_base + g + 8) * ALD + jn * 8 + 2 * tig) = p1;
        }
        __syncwarp();

        // ---- O += P V : packed V frags, LDS.128 ----
#pragma unroll
        for (int s = 0; s < 8; s++) {
            int k8 = s * 8;
            unsigned af[4];
            af[0] = __float_as_uint(Ps[(row_base + g) * ALD + k8 + tig]);
            af[1] = __float_as_uint(Ps[(row_base + g + 8) * ALD + k8 + tig]);
            af[2] = __float_as_uint(Ps[(row_base + g) * ALD + k8 + tig + 4]);
            af[3] = __float_as_uint(Ps[(row_base + g + 8) * ALD + k8 + tig + 4]);
#pragma unroll
            for (int j16 = 0; j16 < 4; j16++) {
                float4 b4 = *(const float4*)(Vs + (s * 4 + j16) * 128 + lane * 4);
                const unsigned* bp = (const unsigned*)&b4;
                mma_m16n8k8(oacc[j16 * 2], af, bp);
                mma_m16n8k8(oacc[j16 * 2 + 1], af, bp + 2);
            }
        }
        __syncwarp();
    }

    // epilogue: packed-A write of O (row = b*SS+s, col = h*64+d)
    const int b = bh >> 4, h = bh & 15;
#pragma unroll
    for (int hf = 0; hf < 2; hf++) {
        float inv = 1.0f / l_i[hf];
        int s = q0 + row_base + g + hf * 8;
        int r = b * SS + s;
#pragma unroll
        for (int jn = 0; jn < 8; jn++) {
            int c = h * DK + jn * 8 + 2 * tig;
            O[packA_addr(r, c)]     = f2tf32f(oacc[jn][2 * hf] * inv);
            O[packA_addr(r, c + 1)] = f2tf32f(oacc[jn][2 * hf + 1] * inv);
        }
    }
}

// ---------------- launch ----------------
extern "C" void kernel_launch(void* const* d_in, const int* in_sizes, int n_in,
                              void* d_out, int out_size) {
    const float* x  = (const float*)d_in[0];
    const float* wq = (const float*)d_in[1];
    const float* wk = (const float*)d_in[2];
    const float* wv = (const float*)d_in[3];
    const float* wo = (const float*)d_in[4];
    float* out = (float*)d_out;

    float *pq, *pk, *pv, *pa, *pxt, *pw4;
    cudaGetSymbolAddress((void**)&pq, g_q);
    cudaGetSymbolAddress((void**)&pk, g_k);
    cudaGetSymbolAddress((void**)&pv, g_v);
    cudaGetSymbolAddress((void**)&pa, g_attn);
    cudaGetSymbolAddress((void**)&pxt, g_xt);
    cudaGetSymbolAddress((void**)&pw4, g_w4);

    static const int attn_smem = 128 * ALD * sizeof(float) + 2 * 8192 * 4; // 100352
    static const int gemm_smem = 2 * GSTG * STGF * sizeof(float);          // 65536
    cudaFuncSetAttribute(attn_mma, cudaFuncAttributeMaxDynamicSharedMemorySize,
                         attn_smem);
    cudaFuncSetAttribute(gemm_pk<0>, cudaFuncAttributeMaxDynamicSharedMemorySize,
                         gemm_smem);
    cudaFuncSetAttribute(gemm_pk<1>, cudaFuncAttributeMaxDynamicSharedMemorySize,
                         gemm_smem);

    const int n4x = MM * DD / 4;
    const int n4w4 = 4 * DD * DD / 4;
    pack_a_kernel<<<(n4x + 255) / 256, 256>>>(x, pxt, n4x);
    pack_w4_kernel<<<(n4w4 + 255) / 256, 256>>>(wq, wk, wv, wo, pw4);

    dim3 gQKV(3 * DD / 128, MM / 128);   // (24, 64)
    gemm_pk<1><<<gQKV, 256, gemm_smem>>>(pxt, pw4, pq, pk, pv);

    dim3 gAttn(SS / 128, BB * HH);       // (16, 64)
    attn_mma<<<gAttn, 256, attn_smem>>>(pq, pk, pv, pa);

    dim3 gOut(DD / 128, MM / 128);       // (8, 64)
    gemm_pk<0><<<gOut, 256, gemm_smem>>>(pa, pw4 + 3 * DD * DD, out, nullptr, nullptr);
}

// round 14
// speedup vs baseline: 4.6864x; 1.0061x over previous
#include <cuda_runtime.h>
#include <cuda_bf16.h>
#include <math.h>

// Problem constants
#define BB 4
#define SS 2048
#define DD 1024
#define HH 16
#define DK 64
#define MM (BB * SS)          // 8192 rows
#define NEG_BIG (-1.0e30f)
// softmax scale with log2(e) folded in: 0.125 * 1.44269504
#define QSCALE 0.1803368801111137f
#define KVSZ 131072           // floats per (b,h) packed K or V (2048*64)

// ---------------- scratch (alloc-free: __device__ globals) ----------------
__device__ float g_q[BB * HH * SS * DK];     // [b,h,s,dk]  (pre-scaled, tf32)
__device__ float g_k[BB * HH * SS * DK];     // packed-B per (b,h): n=s, k=d
__device__ float g_v[BB * HH * SS * DK];     // packed-B per (b,h): n=d, k=s
__device__ float g_attn[MM * DD];            // packed-A layout (tf32)
__device__ float g_xt[MM * DD];              // packed-A layout (tf32)
__device__ float g_w4[4 * DD * DD];          // packed-B layout (tf32)

// ---------------- helpers ----------------
__device__ __forceinline__ unsigned f2tf32(float f) {
    unsigned r;
    asm("cvt.rna.tf32.f32 %0, %1;" : "=r"(r) : "f"(f));
    return r;
}
__device__ __forceinline__ float f2tf32f(float f) {
    return __uint_as_float(f2tf32(f));
}
__device__ __forceinline__ float ex2(float x) {
    float y;
    asm("ex2.approx.f32 %0, %1;" : "=f"(y) : "f"(x));
    return y;
}

__device__ __forceinline__ void mma_m16n8k8(float* d, const unsigned* a,
                                            const unsigned* b) {
    asm volatile(
        "mma.sync.aligned.m16n8k8.row.col.f32.tf32.tf32.f32 "
        "{%0,%1,%2,%3},{%4,%5,%6,%7},{%8,%9},{%0,%1,%2,%3};\n"
        : "+f"(d[0]), "+f"(d[1]), "+f"(d[2]), "+f"(d[3])
        : "r"(a[0]), "r"(a[1]), "r"(a[2]), "r"(a[3]), "r"(b[0]), "r"(b[1]));
}

__device__ __forceinline__ void cp16(void* smem, const void* gmem) {
    unsigned s = (unsigned)__cvta_generic_to_shared(smem);
    asm volatile("cp.async.cg.shared.global [%0], [%1], 16;\n" :: "r"(s), "l"(gmem));
}

// packed-A address: element (r, c); k-tiles per row = 128 (K=1024)
__device__ __forceinline__ size_t packA_addr(int r, int c) {
    return ((size_t)((r >> 4) * 128 + (c >> 3)) << 7) +
           ((r & 7) * 16 + (c & 3) * 4 + ((r >> 3) & 1) + 2 * ((c >> 2) & 1));
}
// packed-B element address within one (b,h) K buffer: n=s (2048), k=d (64)
__device__ __forceinline__ size_t packK_addr(int s, int d) {
    return ((size_t)((s >> 4) * 8 + (d >> 3)) << 7) +
           ((s & 7) * 16 + (d & 3) * 4 + ((d >> 2) & 1) + 2 * ((s >> 3) & 1));
}
// packed-B element address within one (b,h) V buffer: n=d (64), k=s (2048),
// tk-major tiling so a 64-kv slab is contiguous
__device__ __forceinline__ size_t packV_addr(int d, int s) {
    return ((size_t)((s >> 3) * 4 + (d >> 4)) << 7) +
           ((d & 7) * 16 + (s & 3) * 4 + ((s >> 2) & 1) + 2 * ((d >> 3) & 1));
}

// ---------------- pre-pass: pack X (A layout) ----------------
__global__ void pack_a_kernel(const float* __restrict__ A, float* __restrict__ out,
                              int n4) {
    int i = blockIdx.x * blockDim.x + threadIdx.x;
    if (i >= n4) return;
    int tm = i >> 12;
    int tk = (i >> 5) & 127;
    int lane = i & 31;
    int g = lane >> 2, tig = lane & 3;
    int r0 = tm * 16, c0 = tk * 8;
    const float* p = A + (size_t)r0 * DD + c0;
    float4 v;
    v.x = f2tf32f(p[(size_t)g * DD + tig]);
    v.y = f2tf32f(p[(size_t)(g + 8) * DD + tig]);
    v.z = f2tf32f(p[(size_t)g * DD + tig + 4]);
    v.w = f2tf32f(p[(size_t)(g + 8) * DD + tig + 4]);
    ((float4*)out)[i] = v;
}

// ---------------- pre-pass: pack 4 weights (B layout) ----------------
__global__ void pack_w4_kernel(const float* __restrict__ w0,
                               const float* __restrict__ w1,
                               const float* __restrict__ w2,
                               const float* __restrict__ w3,
                               float* __restrict__ out) {
    const int per_w = DD * DD / 4;
    int j = blockIdx.x * blockDim.x + threadIdx.x;
    if (j >= 4 * per_w) return;
    int w = j / per_w, i = j - w * per_w;
    const float* W = (w == 0) ? w0 : (w == 1) ? w1 : (w == 2) ? w2 : w3;
    int tn = i >> 12;
    int tk = (i >> 5) & 127;
    int lane = i & 31;
    int g = lane >> 2, tig = lane & 3;
    int n0 = tn * 16, k0 = tk * 8;
    const float* p = W + (size_t)n0 * DD + k0;
    float4 v;
    v.x = f2tf32f(p[(size_t)g * DD + tig]);
    v.y = f2tf32f(p[(size_t)g * DD + tig + 4]);
    v.z = f2tf32f(p[(size_t)(g + 8) * DD + tig]);
    v.w = f2tf32f(p[(size_t)(g + 8) * DD + tig + 4]);
    ((float4*)(out + (size_t)w * DD * DD))[j - w * per_w] = v;
}

// ---------------- GEMM core: packed A x packed B -> C ----------------
// BM=BN=128, BK=32, 3-stage cp.async. 8 warps, warp tile 64x32.
// MODE 0: C row-major [M,1024] (out projection, raw fp32)
// MODE 1: QKV. Q -> [b,h,s,dk] scaled+tf32; K/V -> packed-B per (b,h), tf32.
#define GSTG 3
#define STGF 4096          // floats per stage per operand (128x32)

template <int MODE>
__global__ __launch_bounds__(256, 2) void gemm_pk(const float* __restrict__ A,
                                                  const float* __restrict__ W,
                                                  float* __restrict__ C0,
                                                  float* __restrict__ C1,
                                                  float* __restrict__ C2) {
    extern __shared__ float gsm[];
    float* As = gsm;                      // [GSTG][8 m-tiles][4 k-tiles][128]
    float* Bs = gsm + GSTG * STGF;

    const int tid = threadIdx.x;
    const int lane = tid & 31;
    const int wid = tid >> 5;
    const int g = lane >> 2;
    const int tig = lane & 3;
    const int wm0 = (wid >> 2) * 64;
    const int wn0 = (wid & 3) * 32;
    const int row0 = blockIdx.y * 128;
    const int col0 = blockIdx.x * 128;

    const float* Abase = A + (size_t)(row0 >> 4) * 16384;
    const float* Wbase = W + (size_t)(col0 >> 4) * 16384;

    float acc[4][4][4];
#pragma unroll
    for (int im = 0; im < 4; im++)
#pragma unroll
        for (int jn = 0; jn < 4; jn++)
#pragma unroll
            for (int q = 0; q < 4; q++) acc[im][jn][q] = 0.0f;

    const int NK = DD / 32;   // 32 iterations of BK=32

    // prologue: stages 0,1
#pragma unroll
    for (int s = 0; s < 2; s++) {
#pragma unroll
        for (int h = 0; h < 4; h++) {
            int c = tid + h * 256;              // 0..1023 chunks of 16B
            int tm_l = c >> 7;                  // 0..7
            int r = c & 127;
            int kk = r >> 5, f4 = r & 31;
            size_t go = (size_t)tm_l * 16384 + (size_t)(s * 4 + kk) * 128 + f4 * 4;
            cp16(As + s * STGF + c * 4, Abase + go);
            cp16(Bs + s * STGF + c * 4, Wbase + go);
        }
        asm volatile("cp.async.commit_group;\n");
    }

    for (int kt = 0; kt < NK; kt++) {
        if (kt < NK - 1) asm volatile("cp.async.wait_group 1;\n");
        else             asm volatile("cp.async.wait_group 0;\n");
        __syncthreads();

        if (kt + 2 < NK) {
            const int nxt = (kt + 2) % 3;
#pragma unroll
            for (int h = 0; h < 4; h++) {
                int c = tid + h * 256;
                int tm_l = c >> 7;
                int r = c & 127;
                int kk = r >> 5, f4 = r & 31;
                size_t go = (size_t)tm_l * 16384 +
                            (size_t)((kt + 2) * 4 + kk) * 128 + f4 * 4;
                cp16(As + nxt * STGF + c * 4, Abase + go);
                cp16(Bs + nxt * STGF + c * 4, Wbase + go);
            }
            asm volatile("cp.async.commit_group;\n");
        }

        const float* Ac = As + (kt % 3) * STGF;
        const float* Bc = Bs + (kt % 3) * STGF;
#pragma unroll
        for (int kk = 0; kk < 4; kk++) {
            float4 af4[4], bf4[2];
#pragma unroll
            for (int im = 0; im < 4; im++)
                af4[im] = *(const float4*)(Ac + (((wm0 >> 4) + im) * 4 + kk) * 128 +
                                           lane * 4);
#pragma unroll
            for (int p = 0; p < 2; p++)
                bf4[p] = *(const float4*)(Bc + (((wn0 >> 4) + p) * 4 + kk) * 128 +
                                          lane * 4);
#pragma unroll
            for (int im = 0; im < 4; im++) {
                const unsigned* a = (const unsigned*)&af4[im];
#pragma unroll
                for (int jn = 0; jn < 4; jn++) {
                    const unsigned* bp = (const unsigned*)&bf4[jn >> 1];
                    unsigned b[2] = {bp[(jn & 1) * 2], bp[(jn & 1) * 2 + 1]};
                    mma_m16n8k8(acc[im][jn], a, b);
                }
            }
        }
    }

#pragma unroll
    for (int im = 0; im < 4; im++) {
#pragma unroll
        for (int jn = 0; jn < 4; jn++) {
            int r = row0 + wm0 + im * 16 + g;
            int c = col0 + wn0 + jn * 8 + 2 * tig;
#pragma unroll
            for (int half = 0; half < 2; half++) {
                int rr = r + half * 8;
                float2 v = make_float2(acc[im][jn][half * 2 + 0],
                                       acc[im][jn][half * 2 + 1]);
                if (MODE == 1) {
                    int w = c >> 10;
                    int cl = c & 1023;
                    int b = rr >> 11;
                    int s = rr & 2047;
                    int h = cl >> 6;
                    int d = cl & 63;
                    if (w == 0) {
                        v.x = f2tf32f(v.x * QSCALE);
                        v.y = f2tf32f(v.y * QSCALE);
                        size_t off = (((size_t)(b * HH + h) * SS + s) * DK + d);
                        *(float2*)(C0 + off) = v;
                    } else if (w == 1) {
                        float* dst = C1 + (size_t)(b * HH + h) * KVSZ;
                        dst[packK_addr(s, d)]     = f2tf32f(v.x);
                        dst[packK_addr(s, d + 1)] = f2tf32f(v.y);
                    } else {
                        float* dst = C2 + (size_t)(b * HH + h) * KVSZ;
                        dst[packV_addr(d, s)]     = f2tf32f(v.x);
                        dst[packV_addr(d + 1, s)] = f2tf32f(v.y);
                    }
                } else {
                    *(float2*)(C0 + (size_t)rr * DD + c) = v;
                }
            }
        }
    }
}

// ---------------- Flash attention (causal), packed K/V fragments ----------
// BM=128, BN=64. 8 warps; warp w owns rows [16w,16w+16).
// K/V arrive in packed-B tile layout -> mainloop frag loads are LDS.128.
// smem: Ps[128*68] + 2 stages x (K 4096 + V 4096) = 100352 B.
#define ALD 68

__global__ __launch_bounds__(256, 2) void attn_mma(const float* __restrict__ Q,
                                                   const float* __restrict__ K,
                                                   const float* __restrict__ V,
                                                   float* __restrict__ O) {
    extern __shared__ float sm[];
    float* Ps = sm;                     // [128][ALD]
    float* KVs = sm + 128 * ALD;        // 2 x [K:4096 | V:4096]

    const int tid = threadIdx.x;
    const int lane = tid & 31;
    const int wid = tid >> 5;
    const int g = lane >> 2;
    const int tig = lane & 3;
    const int qb = (gridDim.x - 1) - blockIdx.x;
    const int bh = blockIdx.y;
    const int q0 = qb * 128;
    const int row_base = wid * 16;

    const float* Qb = Q + (size_t)bh * SS * DK;
    const float* Kb = K + (size_t)bh * KVSZ;
    const float* Vb = V + (size_t)bh * KVSZ;

    // Q fragments straight from gmem (already scaled + tf32)
    unsigned qf[8][4];
    {
        const float* qr0 = Qb + (size_t)(q0 + row_base + g) * DK;
        const float* qr1 = Qb + (size_t)(q0 + row_base + g + 8) * DK;
#pragma unroll
        for (int s = 0; s < 8; s++) {
            int k8 = s * 8;
            qf[s][0] = __float_as_uint(qr0[k8 + tig]);
            qf[s][1] = __float_as_uint(qr1[k8 + tig]);
            qf[s][2] = __float_as_uint(qr0[k8 + tig + 4]);
            qf[s][3] = __float_as_uint(qr1[k8 + tig + 4]);
        }
    }

    float m_i[2] = {NEG_BIG, NEG_BIG};
    float l_i[2] = {0.0f, 0.0f};
    float oacc[8][4];
#pragma unroll
    for (int jn = 0; jn < 8; jn++)
#pragma unroll
        for (int q = 0; q < 4; q++) oacc[jn][q] = 0.0f;

    const int nt = 2 * qb + 2;

    // stage fill: K slab (contiguous 4096) + V slab (contiguous 4096)
    auto fill = [&](int st, int kv0) {
        float* Kd = KVs + st * 8192;
        const float* ks = Kb + (size_t)(kv0 >> 4) * 1024;
        const float* vs = Vb + (size_t)(kv0 >> 3) * 512;
#pragma unroll
        for (int i = 0; i < 4; i++) {
            int idx = tid + 256 * i;        // 0..1023
            cp16(Kd + idx * 4, ks + idx * 4);
        }
#pragma unroll
        for (int i = 0; i < 4; i++) {
            int idx = tid + 256 * i;
            cp16(Kd + 4096 + idx * 4, vs + idx * 4);
        }
        asm volatile("cp.async.commit_group;\n");
    };

    fill(0, 0);

    for (int t = 0; t < nt; t++) {
        asm volatile("cp.async.wait_group 0;\n");
        __syncthreads();

        const int cur = t & 1;
        if (t + 1 < nt) fill(cur ^ 1, (t + 1) * 64);

        // Last kv tile covers cols [q0+64, q0+128): warps 0-3 (rows < q0+64)
        // are fully causally masked there -> skip (exact identity: corr=1, sum=0).
        const bool skip = (t == nt - 1) && (wid < 4);
        if (!skip) {
            const float* Ks = KVs + cur * 8192;
            const float* Vs = Ks + 4096;

            // ---- S = Q K^T : packed K frags, LDS.128 ----
            float sacc[8][4];
#pragma unroll
            for (int jn = 0; jn < 8; jn++)
#pragma unroll
                for (int q = 0; q < 4; q++) sacc[jn][q] = 0.0f;

#pragma unroll
            for (int s = 0; s < 8; s++) {
#pragma unroll
                for (int j16 = 0; j16 < 4; j16++) {
                    float4 b4 = *(const float4*)(Ks + (j16 * 8 + s) * 128 + lane * 4);
                    const unsigned* bp = (const unsigned*)&b4;
                    mma_m16n8k8(sacc[j16 * 2], qf[s], bp);
                    mma_m16n8k8(sacc[j16 * 2 + 1], qf[s], bp + 2);
                }
            }

            // mask: tile nt-1 (warps 4-7 partially), tile nt-2 (warps 0-3 only)
            if (t >= nt - 2 && !(t == nt - 2 && wid >= 4)) {
                const int kv0 = t * 64;
#pragma unroll
                for (int jn = 0; jn < 8; jn++)
#pragma unroll
                    for (int q = 0; q < 4; q++) {
                        int row = q0 + row_base + g + (q >> 1) * 8;
                        int col = kv0 + jn * 8 + 2 * tig + (q & 1);
                        if (col > row) sacc[jn][q] = NEG_BIG;
                    }
            }

            // ---- online softmax (base-2) ----
#pragma unroll
            for (int h = 0; h < 2; h++) {
                float mx = NEG_BIG;
#pragma unroll
                for (int jn = 0; jn < 8; jn++)
                    mx = fmaxf(mx, fmaxf(sacc[jn][2 * h], sacc[jn][2 * h + 1]));
                mx = fmaxf(mx, __shfl_xor_sync(0xffffffffu, mx, 1));
                mx = fmaxf(mx, __shfl_xor_sync(0xffffffffu, mx, 2));
                float mn = fmaxf(m_i[h], mx);
                float corr = ex2(m_i[h] - mn);
                m_i[h] = mn;
                float rs = 0.0f;
#pragma unroll
                for (int jn = 0; jn < 8; jn++) {
                    float e0 = ex2(sacc[jn][2 * h] - mn);
                    float e1 = ex2(sacc[jn][2 * h + 1] - mn);
                    sacc[jn][2 * h] = e0;
                    sacc[jn][2 * h + 1] = e1;
                    rs += e0 + e1;
                }
                rs += __shfl_xor_sync(0xffffffffu, rs, 1);
                rs += __shfl_xor_sync(0xffffffffu, rs, 2);
                l_i[h] = l_i[h] * corr + rs;
#pragma unroll
                for (int jn = 0; jn < 8; jn++) {
                    oacc[jn][2 * h] *= corr;
                    oacc[jn][2 * h + 1] *= corr;
                }
            }

            // ---- P -> smem (warp-local rows) ----
#pragma unroll
            for (int jn = 0; jn < 8; jn++) {
                float2 p0 = make_float2(f2tf32f(sacc[jn][0]), f2tf32f(sacc[jn][1]));
                float2 p1 = make_float2(f2tf32f(sacc[jn][2]), f2tf32f(sacc[jn][3]));
                *(float2*)(Ps + (row_base + g) * ALD + jn * 8 + 2 * tig) = p0;
                *(float2*)(Ps + (row_base + g + 8) * ALD + jn * 8 + 2 * tig) = p1;
            }
            __syncwarp();

            // ---- O += P V : packed V frags, LDS.128 ----
#pragma unroll
            for (int s = 0; s < 8; s++) {
                int k8 = s * 8;
                unsigned af[4];
                af[0] = __float_as_uint(Ps[(row_base + g) * ALD + k8 + tig]);
                af[1] = __float_as_uint(Ps[(row_base + g + 8) * ALD + k8 + tig]);
                af[2] = __float_as_uint(Ps[(row_base + g) * ALD + k8 + tig + 4]);
                af[3] = __float_as_uint(Ps[(row_base + g + 8) * ALD + k8 + tig + 4]);
#pragma unroll
                for (int j16 = 0; j16 < 4; j16++) {
                    float4 b4 = *(const float4*)(Vs + (s * 4 + j16) * 128 + lane * 4);
                    const unsigned* bp = (const unsigned*)&b4;
                    mma_m16n8k8(oacc[j16 * 2], af, bp);
                    mma_m16n8k8(oacc[j16 * 2 + 1], af, bp + 2);
                }
            }
            __syncwarp();
        }
    }

    // epilogue: packed-A write of O (row = b*SS+s, col = h*64+d)
    const int b = bh >> 4, h = bh & 15;
#pragma unroll
    for (int hf = 0; hf < 2; hf++) {
        float inv = 1.0f / l_i[hf];
        int s = q0 + row_base + g + hf * 8;
        int r = b * SS + s;
#pragma unroll
        for (int jn = 0; jn < 8; jn++) {
            int c = h * DK + jn * 8 + 2 * tig;
            O[packA_addr(r, c)]     = f2tf32f(oacc[jn][2 * hf] * inv);
            O[packA_addr(r, c + 1)] = f2tf32f(oacc[jn][2 * hf + 1] * inv);
        }
    }
}

// ---------------- launch ----------------
extern "C" void kernel_launch(void* const* d_in, const int* in_sizes, int n_in,
                              void* d_out, int out_size) {
    const float* x  = (const float*)d_in[0];
    const float* wq = (const float*)d_in[1];
    const float* wk = (const float*)d_in[2];
    const float* wv = (const float*)d_in[3];
    const float* wo = (const float*)d_in[4];
    float* out = (float*)d_out;

    float *pq, *pk, *pv, *pa, *pxt, *pw4;
    cudaGetSymbolAddress((void**)&pq, g_q);
    cudaGetSymbolAddress((void**)&pk, g_k);
    cudaGetSymbolAddress((void**)&pv, g_v);
    cudaGetSymbolAddress((void**)&pa, g_attn);
    cudaGetSymbolAddress((void**)&pxt, g_xt);
    cudaGetSymbolAddress((void**)&pw4, g_w4);

    static const int attn_smem = 128 * ALD * sizeof(float) + 2 * 8192 * 4; // 100352
    static const int gemm_smem = 2 * GSTG * STGF * sizeof(float);          // 98304
    cudaFuncSetAttribute(attn_mma, cudaFuncAttributeMaxDynamicSharedMemorySize,
                         attn_smem);
    cudaFuncSetAttribute(gemm_pk<0>, cudaFuncAttributeMaxDynamicSharedMemorySize,
                         gemm_smem);
    cudaFuncSetAttribute(gemm_pk<1>, cudaFuncAttributeMaxDynamicSharedMemorySize,
                         gemm_smem);

    const int n4x = MM * DD / 4;
    const int n4w4 = 4 * DD * DD / 4;
    pack_a_kernel<<<(n4x + 255) / 256, 256>>>(x, pxt, n4x);
    pack_w4_kernel<<<(n4w4 + 255) / 256, 256>>>(wq, wk, wv, wo, pw4);

    dim3 gQKV(3 * DD / 128, MM / 128);   // (24, 64)
    gemm_pk<1><<<gQKV, 256, gemm_smem>>>(pxt, pw4, pq, pk, pv);

    dim3 gAttn(SS / 128, BB * HH);       // (16, 64)
    attn_mma<<<gAttn, 256, attn_smem>>>(pq, pk, pv, pa);

    dim3 gOut(DD / 128, MM / 128);       // (8, 64)
    gemm_pk<0><<<gOut, 256, gemm_smem>>>(pa, pw4 + 3 * DD * DD, out, nullptr, nullptr);
}